// round 3
// baseline (speedup 1.0000x reference)
#include <cuda_runtime.h>
#include <cstdint>

#define NEG_SLOPE 0.1f
__device__ __forceinline__ float lrelu(float v) { return v >= 0.f ? v : NEG_SLOPE * v; }

// ---------------- static scratch (no runtime allocation allowed) ----------------
#define MAXN 50176
__device__ __align__(16) float g_x[MAXN * 40];     // [N,40] encoder output (pose | view)
__device__ __align__(16) float g_agg[MAXN * 40];   // [N,40] neighbor sum
__device__ __align__(16) float g_h0[MAXN * 256];
__device__ __align__(16) float g_h1[MAXN * 256];
__device__ int g_is64;

// ---------------- encoder: conv1d(3->9,k3,s2) -> lrelu -> conv1d(9->1,k3,s2) -> lrelu ----
__global__ void encoder_kernel(const float* __restrict__ pose,
                               const float* __restrict__ views,
                               const float* __restrict__ w_e1, const float* __restrict__ b_e1,
                               const float* __restrict__ w_e2, const float* __restrict__ b_e2,
                               int N) {
    __shared__ float sw1[81], sb1[9], sw2[27], sb2;
    int t = threadIdx.x;
    if (t < 81) sw1[t] = w_e1[t];
    if (t < 9)  sb1[t] = b_e1[t];
    if (t >= 96 && t < 123) sw2[t - 96] = w_e2[t - 96];
    if (t == 127) sb2 = b_e2[0];
    __syncthreads();

    int n = blockIdx.x * blockDim.x + threadIdx.x;
    if (n >= N) return;

    // zero agg row for this node (scatter kernel runs after this kernel)
    float4* a4 = (float4*)(g_agg + (size_t)n * 40);
#pragma unroll
    for (int i = 0; i < 10; i++) a4[i] = make_float4(0.f, 0.f, 0.f, 0.f);

    float* xo = g_x + (size_t)n * 40;
    xo[0] = pose[n * 3 + 0];
    xo[1] = pose[n * 3 + 1];
    xo[2] = pose[n * 3 + 2];

    const float* vin = views + (size_t)n * 453;  // [3][151]

    // conv1 at position p: window start 2p over 3 input channels, 9 out channels, lrelu
    float cur[9];
    {
        float in[3][3];
#pragma unroll
        for (int ci = 0; ci < 3; ci++)
#pragma unroll
            for (int k = 0; k < 3; k++) in[ci][k] = vin[ci * 151 + k];
#pragma unroll
        for (int c1 = 0; c1 < 9; c1++) {
            float a = sb1[c1];
#pragma unroll
            for (int ci = 0; ci < 3; ci++)
#pragma unroll
                for (int k = 0; k < 3; k++) a += sw1[c1 * 9 + ci * 3 + k] * in[ci][k];
            cur[c1] = lrelu(a);
        }
    }

    for (int tt = 0; tt < 37; tt++) {
        float b9[9], c9[9];
        // conv1 positions 2t+1 and 2t+2
#pragma unroll
        for (int which = 0; which < 2; which++) {
            int pos = 2 * tt + 1 + which;
            float in[3][3];
#pragma unroll
            for (int ci = 0; ci < 3; ci++)
#pragma unroll
                for (int k = 0; k < 3; k++) in[ci][k] = vin[ci * 151 + 2 * pos + k];
            float* dst = which == 0 ? b9 : c9;
#pragma unroll
            for (int c1 = 0; c1 < 9; c1++) {
                float a = sb1[c1];
#pragma unroll
                for (int ci = 0; ci < 3; ci++)
#pragma unroll
                    for (int k = 0; k < 3; k++) a += sw1[c1 * 9 + ci * 3 + k] * in[ci][k];
                dst[c1] = lrelu(a);
            }
        }
        float acc = sb2;
#pragma unroll
        for (int c1 = 0; c1 < 9; c1++)
            acc += cur[c1] * sw2[c1 * 3 + 0] + b9[c1] * sw2[c1 * 3 + 1] + c9[c1] * sw2[c1 * 3 + 2];
        xo[3 + tt] = lrelu(acc);
#pragma unroll
        for (int c1 = 0; c1 < 9; c1++) cur[c1] = c9[c1];
    }
}

// ---------------- edge index dtype detection (int64 vs int32, data-driven) -----------
__global__ void detect_kernel(const unsigned* __restrict__ p) {
    if (blockIdx.x == 0 && threadIdx.x == 0) {
        bool all0 = true;
        for (int i = 0; i < 256; i++)
            if (p[2 * i + 1] != 0u) { all0 = false; break; }
        g_is64 = all0 ? 1 : 0;  // int64 little-endian: odd 32-bit words are 0 (values < 2^31)
    }
}

// ---------------- scatter: agg[dst] += x[src] over all edges ----------------
__global__ void scatter_kernel(const void* __restrict__ eidx, int E) {
    int e = blockIdx.x * blockDim.x + threadIdx.x;
    if (e >= E) return;
    int src, dst;
    if (g_is64) {
        const long long* p = (const long long*)eidx;
        src = (int)p[e];
        dst = (int)p[(size_t)E + e];
    } else {
        const int* p = (const int*)eidx;
        src = p[e];
        dst = p[E + e];
    }
    const float4* xs = (const float4*)(g_x + (size_t)src * 40);
    float4* ad = (float4*)(g_agg + (size_t)dst * 40);
#pragma unroll
    for (int i = 0; i < 10; i++) {
        float4 v = xs[i];
        atomicAdd(ad + i, v);  // sm_90+ vector reduction (red.global.add.v4.f32)
    }
}

// ---------------- GEMM: first layer, K=80 virtual concat [agg|x] @ [w_rel|w_root]^T + b_rel
// C[M,256] = lrelu( agg @ w_rel^T + b_rel + x @ w_root^T )
__global__ void gemm_first(const float* __restrict__ w_rel, const float* __restrict__ w_root,
                           const float* __restrict__ b_rel, float* __restrict__ C, int M) {
    __shared__ float As[8][132];
    __shared__ float Bs[8][132];
    int tid = threadIdx.x;
    int mB = blockIdx.x * 128;
    int nB = blockIdx.y * 128;
    int m0 = (tid >> 4) * 8, n0 = (tid & 15) * 8;
    float acc[8][8] = {};

    for (int k0 = 0; k0 < 80; k0 += 8) {
#pragma unroll
        for (int i = 0; i < 4; i++) {
            int idx = tid + i * 256;
            int k = idx & 7, r = idx >> 3;
            int kk = k0 + k;
            int m = mB + r;
            float av = 0.f;
            if (m < M)
                av = (kk < 40) ? g_agg[(size_t)m * 40 + kk] : g_x[(size_t)m * 40 + kk - 40];
            As[k][r] = av;
            int n = nB + r;
            Bs[k][r] = (kk < 40) ? w_rel[(size_t)n * 40 + kk] : w_root[(size_t)n * 40 + kk - 40];
        }
        __syncthreads();
#pragma unroll
        for (int k = 0; k < 8; k++) {
            float a[8], b[8];
#pragma unroll
            for (int i = 0; i < 8; i++) a[i] = As[k][m0 + i];
#pragma unroll
            for (int j = 0; j < 8; j++) b[j] = Bs[k][n0 + j];
#pragma unroll
            for (int i = 0; i < 8; i++)
#pragma unroll
                for (int j = 0; j < 8; j++) acc[i][j] += a[i] * b[j];
        }
        __syncthreads();
    }
#pragma unroll
    for (int i = 0; i < 8; i++) {
        int m = mB + m0 + i;
        if (m >= M) break;
#pragma unroll
        for (int j = 0; j < 8; j++)
            C[(size_t)m * 256 + nB + n0 + j] = lrelu(acc[i][j] + b_rel[nB + n0 + j]);
    }
}

// ---------------- GEMM: middle layers, C = lrelu(A[M,256] @ W[256,256]^T + b) -------------
__global__ void gemm_mid(const float* __restrict__ A, const float* __restrict__ W,
                         const float* __restrict__ bias, float* __restrict__ C, int M) {
    const int K = 256;
    __shared__ float As[8][132];
    __shared__ float Bs[8][132];
    int tid = threadIdx.x;
    int mB = blockIdx.x * 128;
    int nB = blockIdx.y * 128;
    int m0 = (tid >> 4) * 8, n0 = (tid & 15) * 8;
    float acc[8][8] = {};

    for (int k0 = 0; k0 < K; k0 += 8) {
#pragma unroll
        for (int i = 0; i < 4; i++) {
            int idx = tid + i * 256;
            int k = idx & 7, r = idx >> 3;
            int m = mB + r;
            As[k][r] = (m < M) ? A[(size_t)m * K + k0 + k] : 0.f;
            Bs[k][r] = W[(size_t)(nB + r) * K + k0 + k];
        }
        __syncthreads();
#pragma unroll
        for (int k = 0; k < 8; k++) {
            float a[8], b[8];
#pragma unroll
            for (int i = 0; i < 8; i++) a[i] = As[k][m0 + i];
#pragma unroll
            for (int j = 0; j < 8; j++) b[j] = Bs[k][n0 + j];
#pragma unroll
            for (int i = 0; i < 8; i++)
#pragma unroll
                for (int j = 0; j < 8; j++) acc[i][j] += a[i] * b[j];
        }
        __syncthreads();
    }
#pragma unroll
    for (int i = 0; i < 8; i++) {
        int m = mB + m0 + i;
        if (m >= M) break;
#pragma unroll
        for (int j = 0; j < 8; j++)
            C[(size_t)m * 256 + nB + n0 + j] = lrelu(acc[i][j] + bias[nB + n0 + j]);
    }
}

// ---------------- pred: out[m] = h[m,:] . w_pred + b_pred ----------------
__global__ void pred_kernel(const float* __restrict__ H, const float* __restrict__ w,
                            const float* __restrict__ b, float* __restrict__ out, int M) {
    int warp = (blockIdx.x * blockDim.x + threadIdx.x) >> 5;
    int lane = threadIdx.x & 31;
    if (warp >= M) return;
    const float* h = H + (size_t)warp * 256;
    float s = 0.f;
#pragma unroll
    for (int i = 0; i < 8; i++) s += h[lane + 32 * i] * w[lane + 32 * i];
#pragma unroll
    for (int o = 16; o; o >>= 1) s += __shfl_down_sync(0xffffffffu, s, o);
    if (lane == 0) out[warp] = s + b[0];
}

extern "C" void kernel_launch(void* const* d_in, const int* in_sizes, int n_in,
                              void* d_out, int out_size) {
    const float* pose   = (const float*)d_in[0];
    const float* views  = (const float*)d_in[1];
    const void*  eidx   = d_in[2];
    const float* w_e1   = (const float*)d_in[3];
    const float* b_e1   = (const float*)d_in[4];
    const float* w_e2   = (const float*)d_in[5];
    const float* b_e2   = (const float*)d_in[6];
    const float* w_rel  = (const float*)d_in[7];
    const float* b_rel  = (const float*)d_in[8];
    const float* w_root = (const float*)d_in[9];
    const float* w_l1   = (const float*)d_in[10];
    const float* b_l1   = (const float*)d_in[11];
    const float* w_l2   = (const float*)d_in[12];
    const float* b_l2   = (const float*)d_in[13];
    const float* w_l3   = (const float*)d_in[14];
    const float* b_l3   = (const float*)d_in[15];
    const float* w_pred = (const float*)d_in[16];
    const float* b_pred = (const float*)d_in[17];
    float* out = (float*)d_out;

    int N = in_sizes[0] / 3;
    int E = in_sizes[2] / 2;

    float *h0, *h1;
    cudaGetSymbolAddress((void**)&h0, g_h0);
    cudaGetSymbolAddress((void**)&h1, g_h1);

    encoder_kernel<<<(N + 255) / 256, 256>>>(pose, views, w_e1, b_e1, w_e2, b_e2, N);
    detect_kernel<<<1, 32>>>((const unsigned*)eidx);
    scatter_kernel<<<(E + 255) / 256, 256>>>(eidx, E);

    dim3 ggrid((N + 127) / 128, 2);
    gemm_first<<<ggrid, 256>>>(w_rel, w_root, b_rel, h0, N);
    gemm_mid<<<ggrid, 256>>>(h0, w_l1, b_l1, h1, N);
    gemm_mid<<<ggrid, 256>>>(h1, w_l2, b_l2, h0, N);
    gemm_mid<<<ggrid, 256>>>(h0, w_l3, b_l3, h1, N);
    pred_kernel<<<(N * 32 + 255) / 256, 256>>>(h1, w_pred, b_pred, out, N);
}

// round 4
// speedup vs baseline: 1.5358x; 1.5358x over previous
#include <cuda_runtime.h>
#include <cstdint>

#define NEG_SLOPE 0.1f
__device__ __forceinline__ float lrelu(float v) { return v >= 0.f ? v : NEG_SLOPE * v; }

// ---------------- static scratch ----------------
#define MAXN 50176
__device__ __align__(16) float g_xc[MAXN * 80];    // [N,80]: cols 0..39 agg (atomics), 40..79 x
__device__ __align__(16) float g_w1cat[256 * 80];  // [256,80] = [w_rel | w_root]
__device__ __align__(16) float g_h0[MAXN * 256];
__device__ __align__(16) float g_h1[MAXN * 256];
__device__ int g_is64;

__device__ __forceinline__ uint32_t f2tf32(float f) {
    uint32_t r;
    asm("cvt.rna.tf32.f32 %0, %1;" : "=r"(r) : "f"(f));
    return r;
}

// ---------------- encoder: conv1d(3->9,k3,s2)->lrelu->conv1d(9->1,k3,s2)->lrelu ----
__global__ void encoder_kernel(const float* __restrict__ pose,
                               const float* __restrict__ views,
                               const float* __restrict__ w_e1, const float* __restrict__ b_e1,
                               const float* __restrict__ w_e2, const float* __restrict__ b_e2,
                               int N) {
    __shared__ float sw1[81], sb1[9], sw2[27], sb2;
    int t = threadIdx.x;
    if (t < 81) sw1[t] = w_e1[t];
    if (t < 9)  sb1[t] = b_e1[t];
    if (t >= 96 && t < 123) sw2[t - 96] = w_e2[t - 96];
    if (t == 127) sb2 = b_e2[0];
    __syncthreads();

    int n = blockIdx.x * blockDim.x + threadIdx.x;
    if (n >= N) return;

    float* row = g_xc + (size_t)n * 80;
    float4* a4 = (float4*)row;                 // zero agg region (cols 0..39)
#pragma unroll
    for (int i = 0; i < 10; i++) a4[i] = make_float4(0.f, 0.f, 0.f, 0.f);

    float* xo = row + 40;
    xo[0] = pose[n * 3 + 0];
    xo[1] = pose[n * 3 + 1];
    xo[2] = pose[n * 3 + 2];

    const float* vin = views + (size_t)n * 453;  // [3][151]

    float cur[9];
    {
        float in[3][3];
#pragma unroll
        for (int ci = 0; ci < 3; ci++)
#pragma unroll
            for (int k = 0; k < 3; k++) in[ci][k] = vin[ci * 151 + k];
#pragma unroll
        for (int c1 = 0; c1 < 9; c1++) {
            float a = sb1[c1];
#pragma unroll
            for (int ci = 0; ci < 3; ci++)
#pragma unroll
                for (int k = 0; k < 3; k++) a += sw1[c1 * 9 + ci * 3 + k] * in[ci][k];
            cur[c1] = lrelu(a);
        }
    }

    for (int tt = 0; tt < 37; tt++) {
        float b9[9], c9[9];
#pragma unroll
        for (int which = 0; which < 2; which++) {
            int pos = 2 * tt + 1 + which;
            float in[3][3];
#pragma unroll
            for (int ci = 0; ci < 3; ci++)
#pragma unroll
                for (int k = 0; k < 3; k++) in[ci][k] = vin[ci * 151 + 2 * pos + k];
            float* dst = which == 0 ? b9 : c9;
#pragma unroll
            for (int c1 = 0; c1 < 9; c1++) {
                float a = sb1[c1];
#pragma unroll
                for (int ci = 0; ci < 3; ci++)
#pragma unroll
                    for (int k = 0; k < 3; k++) a += sw1[c1 * 9 + ci * 3 + k] * in[ci][k];
                dst[c1] = lrelu(a);
            }
        }
        float acc = sb2;
#pragma unroll
        for (int c1 = 0; c1 < 9; c1++)
            acc += cur[c1] * sw2[c1 * 3 + 0] + b9[c1] * sw2[c1 * 3 + 1] + c9[c1] * sw2[c1 * 3 + 2];
        xo[3 + tt] = lrelu(acc);
#pragma unroll
        for (int c1 = 0; c1 < 9; c1++) cur[c1] = c9[c1];
    }
}

// ---------------- pack [w_rel | w_root] into one [256,80] matrix ----------------
__global__ void pack_w1(const float* __restrict__ w_rel, const float* __restrict__ w_root) {
    int i = blockIdx.x * blockDim.x + threadIdx.x;
    if (i >= 256 * 80) return;
    int n = i / 80, j = i % 80;
    g_w1cat[i] = (j < 40) ? w_rel[n * 40 + j] : w_root[n * 40 + j - 40];
}

// ---------------- edge index dtype detection ----------------
__global__ void detect_kernel(const unsigned* __restrict__ p) {
    if (blockIdx.x == 0 && threadIdx.x == 0) {
        bool all0 = true;
        for (int i = 0; i < 256; i++)
            if (p[2 * i + 1] != 0u) { all0 = false; break; }
        g_is64 = all0 ? 1 : 0;
    }
}

// ---------------- scatter: agg[dst] += x[src] ----------------
__global__ void scatter_kernel(const void* __restrict__ eidx, int E) {
    int e = blockIdx.x * blockDim.x + threadIdx.x;
    if (e >= E) return;
    int src, dst;
    if (g_is64) {
        const long long* p = (const long long*)eidx;
        src = (int)p[e];
        dst = (int)p[(size_t)E + e];
    } else {
        const int* p = (const int*)eidx;
        src = p[e];
        dst = p[E + e];
    }
    const float4* xs = (const float4*)(g_xc + (size_t)src * 80 + 40);
    float4* ad = (float4*)(g_xc + (size_t)dst * 80);
#pragma unroll
    for (int i = 0; i < 10; i++) {
        float4 v = xs[i];
        atomicAdd(ad + i, v);
    }
}

// ---------------- tf32 tensor-core GEMM: C[M,256] = act(A[M,K] @ B[256,K]^T + bias) ----
// block tile 128x128, 8 warps (2x4), warp tile 64x32, BLK_K=32
__device__ __forceinline__ void mma_tf32(float c[4], const uint32_t a[4], const uint32_t b[2]) {
    asm volatile(
        "mma.sync.aligned.m16n8k8.row.col.f32.tf32.tf32.f32 "
        "{%0,%1,%2,%3}, {%4,%5,%6,%7}, {%8,%9}, {%0,%1,%2,%3};\n"
        : "+f"(c[0]), "+f"(c[1]), "+f"(c[2]), "+f"(c[3])
        : "r"(a[0]), "r"(a[1]), "r"(a[2]), "r"(a[3]), "r"(b[0]), "r"(b[1]));
}

template <int APPLY_LRELU>
__global__ __launch_bounds__(256, 2)
void gemm_tf32(const float* __restrict__ A, const float* __restrict__ B,
               const float* __restrict__ bias, float* __restrict__ C, int M, int K) {
    __shared__ uint32_t As[128][36];  // [m][k], stride 36 (==4 mod 32 -> conflict-free frags)
    __shared__ uint32_t Bs[128][36];  // [n][k]

    int tid = threadIdx.x;
    int mB = blockIdx.x * 128;
    int nB = blockIdx.y * 128;
    int wid = tid >> 5, lane = tid & 31;
    int wm = wid >> 2;       // 0..1 -> 64 rows
    int wn = wid & 3;        // 0..3 -> 32 cols
    int g = lane >> 2, t = lane & 3;

    float c[4][4][4];
#pragma unroll
    for (int i = 0; i < 4; i++)
#pragma unroll
        for (int j = 0; j < 4; j++)
#pragma unroll
            for (int r = 0; r < 4; r++) c[i][j][r] = 0.f;

    for (int k0 = 0; k0 < K; k0 += 32) {
        // load A,B tiles (128x32) -> smem as tf32
#pragma unroll
        for (int p = 0; p < 4; p++) {
            int lin = tid + p * 256;
            int r = lin >> 3, cq = lin & 7;
            int k = k0 + cq * 4;
            // A
            {
                int m = mB + r;
                float4 v = make_float4(0.f, 0.f, 0.f, 0.f);
                if (m < M) {
                    if (k + 3 < K) v = *(const float4*)(A + (size_t)m * K + k);
                    else {
                        if (k + 0 < K) v.x = A[(size_t)m * K + k + 0];
                        if (k + 1 < K) v.y = A[(size_t)m * K + k + 1];
                        if (k + 2 < K) v.z = A[(size_t)m * K + k + 2];
                        if (k + 3 < K) v.w = A[(size_t)m * K + k + 3];
                    }
                }
                uint4 u = make_uint4(f2tf32(v.x), f2tf32(v.y), f2tf32(v.z), f2tf32(v.w));
                *(uint4*)&As[r][cq * 4] = u;
            }
            // B
            {
                int n = nB + r;
                float4 v = make_float4(0.f, 0.f, 0.f, 0.f);
                if (k + 3 < K) v = *(const float4*)(B + (size_t)n * K + k);
                else {
                    if (k + 0 < K) v.x = B[(size_t)n * K + k + 0];
                    if (k + 1 < K) v.y = B[(size_t)n * K + k + 1];
                    if (k + 2 < K) v.z = B[(size_t)n * K + k + 2];
                    if (k + 3 < K) v.w = B[(size_t)n * K + k + 3];
                }
                uint4 u = make_uint4(f2tf32(v.x), f2tf32(v.y), f2tf32(v.z), f2tf32(v.w));
                *(uint4*)&Bs[r][cq * 4] = u;
            }
        }
        __syncthreads();

#pragma unroll
        for (int kk = 0; kk < 32; kk += 8) {
            uint32_t a[4][4], b[4][2];
#pragma unroll
            for (int mt = 0; mt < 4; mt++) {
                int m = wm * 64 + mt * 16 + g;
                a[mt][0] = As[m][kk + t];
                a[mt][1] = As[m + 8][kk + t];
                a[mt][2] = As[m][kk + t + 4];
                a[mt][3] = As[m + 8][kk + t + 4];
            }
#pragma unroll
            for (int nt = 0; nt < 4; nt++) {
                int n = wn * 32 + nt * 8 + g;
                b[nt][0] = Bs[n][kk + t];
                b[nt][1] = Bs[n][kk + t + 4];
            }
#pragma unroll
            for (int mt = 0; mt < 4; mt++)
#pragma unroll
                for (int nt = 0; nt < 4; nt++) mma_tf32(c[mt][nt], a[mt], b[nt]);
        }
        __syncthreads();
    }

    // epilogue: bias + lrelu, float2 stores
#pragma unroll
    for (int mt = 0; mt < 4; mt++) {
#pragma unroll
        for (int nt = 0; nt < 4; nt++) {
            int m0 = mB + wm * 64 + mt * 16 + g;
            int n0 = nB + wn * 32 + nt * 8 + 2 * t;
            float bx = bias[n0], by = bias[n0 + 1];
            if (m0 < M) {
                float2 v;
                v.x = c[mt][nt][0] + bx;
                v.y = c[mt][nt][1] + by;
                if (APPLY_LRELU) { v.x = lrelu(v.x); v.y = lrelu(v.y); }
                *(float2*)(C + (size_t)m0 * 256 + n0) = v;
            }
            if (m0 + 8 < M) {
                float2 v;
                v.x = c[mt][nt][2] + bx;
                v.y = c[mt][nt][3] + by;
                if (APPLY_LRELU) { v.x = lrelu(v.x); v.y = lrelu(v.y); }
                *(float2*)(C + (size_t)(m0 + 8) * 256 + n0) = v;
            }
        }
    }
}

// ---------------- pred: out[m] = h[m,:] . w_pred + b_pred ----------------
__global__ void pred_kernel(const float* __restrict__ H, const float* __restrict__ w,
                            const float* __restrict__ b, float* __restrict__ out, int M) {
    int warp = (blockIdx.x * blockDim.x + threadIdx.x) >> 5;
    int lane = threadIdx.x & 31;
    if (warp >= M) return;
    const float* h = H + (size_t)warp * 256;
    float s = 0.f;
#pragma unroll
    for (int i = 0; i < 8; i++) s += h[lane + 32 * i] * w[lane + 32 * i];
#pragma unroll
    for (int o = 16; o; o >>= 1) s += __shfl_down_sync(0xffffffffu, s, o);
    if (lane == 0) out[warp] = s + b[0];
}

extern "C" void kernel_launch(void* const* d_in, const int* in_sizes, int n_in,
                              void* d_out, int out_size) {
    const float* pose   = (const float*)d_in[0];
    const float* views  = (const float*)d_in[1];
    const void*  eidx   = d_in[2];
    const float* w_e1   = (const float*)d_in[3];
    const float* b_e1   = (const float*)d_in[4];
    const float* w_e2   = (const float*)d_in[5];
    const float* b_e2   = (const float*)d_in[6];
    const float* w_rel  = (const float*)d_in[7];
    const float* b_rel  = (const float*)d_in[8];
    const float* w_root = (const float*)d_in[9];
    const float* w_l1   = (const float*)d_in[10];
    const float* b_l1   = (const float*)d_in[11];
    const float* w_l2   = (const float*)d_in[12];
    const float* b_l2   = (const float*)d_in[13];
    const float* w_l3   = (const float*)d_in[14];
    const float* b_l3   = (const float*)d_in[15];
    const float* w_pred = (const float*)d_in[16];
    const float* b_pred = (const float*)d_in[17];
    float* out = (float*)d_out;

    int N = in_sizes[0] / 3;
    int E = in_sizes[2] / 2;

    float *xc, *w1, *h0, *h1;
    cudaGetSymbolAddress((void**)&xc, g_xc);
    cudaGetSymbolAddress((void**)&w1, g_w1cat);
    cudaGetSymbolAddress((void**)&h0, g_h0);
    cudaGetSymbolAddress((void**)&h1, g_h1);

    encoder_kernel<<<(N + 255) / 256, 256>>>(pose, views, w_e1, b_e1, w_e2, b_e2, N);
    pack_w1<<<(256 * 80 + 255) / 256, 256>>>(w_rel, w_root);
    detect_kernel<<<1, 32>>>((const unsigned*)eidx);
    scatter_kernel<<<(E + 255) / 256, 256>>>(eidx, E);

    dim3 ggrid((N + 127) / 128, 2);
    gemm_tf32<1><<<ggrid, 256>>>(xc, w1, b_rel, h0, N, 80);
    gemm_tf32<1><<<ggrid, 256>>>(h0, w_l1, b_l1, h1, N, 256);
    gemm_tf32<1><<<ggrid, 256>>>(h1, w_l2, b_l2, h0, N, 256);
    gemm_tf32<1><<<ggrid, 256>>>(h0, w_l3, b_l3, h1, N, 256);
    pred_kernel<<<(N * 32 + 255) / 256, 256>>>(h1, w_pred, b_pred, out, N);
}

// round 5
// speedup vs baseline: 1.6833x; 1.0960x over previous
#include <cuda_runtime.h>
#include <cstdint>

#define NEG_SLOPE 0.1f
__device__ __forceinline__ float lrelu(float v) { return v >= 0.f ? v : NEG_SLOPE * v; }

// ---------------- static scratch ----------------
#define MAXN 50176
#define MAXE 5000000
__device__ __align__(16) float g_xc[MAXN * 80];    // [N,80]: cols 0..39 agg, 40..79 x
__device__ __align__(16) float g_w1cat[256 * 80];  // [256,80] = [w_rel | w_root]
__device__ __align__(16) float g_h0[MAXN * 256];
__device__ __align__(16) float g_h1[MAXN * 256];
__device__ int g_cnt[MAXN];
__device__ int g_off[MAXN + 1];
__device__ int g_cur[MAXN];
__device__ int g_esrc[MAXE];
__device__ int g_is64;

__device__ __forceinline__ uint32_t f2tf32(float f) {
    uint32_t r;
    asm("cvt.rna.tf32.f32 %0, %1;" : "=r"(r) : "f"(f));
    return r;
}

// ---------------- encoder ----------------
__global__ void encoder_kernel(const float* __restrict__ pose,
                               const float* __restrict__ views,
                               const float* __restrict__ w_e1, const float* __restrict__ b_e1,
                               const float* __restrict__ w_e2, const float* __restrict__ b_e2,
                               int N) {
    __shared__ float sw1[81], sb1[9], sw2[27], sb2;
    int t = threadIdx.x;
    if (t < 81) sw1[t] = w_e1[t];
    if (t < 9)  sb1[t] = b_e1[t];
    if (t >= 96 && t < 123) sw2[t - 96] = w_e2[t - 96];
    if (t == 127) sb2 = b_e2[0];
    __syncthreads();

    int n = blockIdx.x * blockDim.x + threadIdx.x;
    if (n >= N) return;

    float* row = g_xc + (size_t)n * 80;
    float* xo = row + 40;
    xo[0] = pose[n * 3 + 0];
    xo[1] = pose[n * 3 + 1];
    xo[2] = pose[n * 3 + 2];

    const float* vin = views + (size_t)n * 453;  // [3][151]

    float cur[9];
    {
        float in[3][3];
#pragma unroll
        for (int ci = 0; ci < 3; ci++)
#pragma unroll
            for (int k = 0; k < 3; k++) in[ci][k] = vin[ci * 151 + k];
#pragma unroll
        for (int c1 = 0; c1 < 9; c1++) {
            float a = sb1[c1];
#pragma unroll
            for (int ci = 0; ci < 3; ci++)
#pragma unroll
                for (int k = 0; k < 3; k++) a += sw1[c1 * 9 + ci * 3 + k] * in[ci][k];
            cur[c1] = lrelu(a);
        }
    }

    for (int tt = 0; tt < 37; tt++) {
        float b9[9], c9[9];
#pragma unroll
        for (int which = 0; which < 2; which++) {
            int pos = 2 * tt + 1 + which;
            float in[3][3];
#pragma unroll
            for (int ci = 0; ci < 3; ci++)
#pragma unroll
                for (int k = 0; k < 3; k++) in[ci][k] = vin[ci * 151 + 2 * pos + k];
            float* dst = which == 0 ? b9 : c9;
#pragma unroll
            for (int c1 = 0; c1 < 9; c1++) {
                float a = sb1[c1];
#pragma unroll
                for (int ci = 0; ci < 3; ci++)
#pragma unroll
                    for (int k = 0; k < 3; k++) a += sw1[c1 * 9 + ci * 3 + k] * in[ci][k];
                dst[c1] = lrelu(a);
            }
        }
        float acc = sb2;
#pragma unroll
        for (int c1 = 0; c1 < 9; c1++)
            acc += cur[c1] * sw2[c1 * 3 + 0] + b9[c1] * sw2[c1 * 3 + 1] + c9[c1] * sw2[c1 * 3 + 2];
        xo[3 + tt] = lrelu(acc);
#pragma unroll
        for (int c1 = 0; c1 < 9; c1++) cur[c1] = c9[c1];
    }
}

// ---------------- pack [w_rel | w_root] ----------------
__global__ void pack_w1(const float* __restrict__ w_rel, const float* __restrict__ w_root) {
    int i = blockIdx.x * blockDim.x + threadIdx.x;
    if (i >= 256 * 80) return;
    int n = i / 80, j = i % 80;
    g_w1cat[i] = (j < 40) ? w_rel[n * 40 + j] : w_root[n * 40 + j - 40];
}

// ---------------- edge index dtype detection ----------------
__global__ void detect_kernel(const unsigned* __restrict__ p) {
    if (blockIdx.x == 0 && threadIdx.x == 0) {
        bool all0 = true;
        for (int i = 0; i < 256; i++)
            if (p[2 * i + 1] != 0u) { all0 = false; break; }
        g_is64 = all0 ? 1 : 0;
    }
}

// ---------------- CSR build: count / scan / fill ----------------
__global__ void count_kernel(const void* __restrict__ eidx, int E) {
    int e = blockIdx.x * blockDim.x + threadIdx.x;
    if (e >= E) return;
    int dst;
    if (g_is64) dst = (int)((const long long*)eidx)[(size_t)E + e];
    else        dst = ((const int*)eidx)[E + e];
    atomicAdd(&g_cnt[dst], 1);
}

__global__ void scan_kernel(int N) {
    __shared__ int s[1024];
    __shared__ int carry_s;
    int t = threadIdx.x;
    if (t == 0) carry_s = 0;
    __syncthreads();
    for (int base = 0; base < N; base += 1024) {
        int i = base + t;
        int v = (i < N) ? g_cnt[i] : 0;
        s[t] = v;
        __syncthreads();
#pragma unroll
        for (int o = 1; o < 1024; o <<= 1) {
            int tmp = (t >= o) ? s[t - o] : 0;
            __syncthreads();
            s[t] += tmp;
            __syncthreads();
        }
        int excl = carry_s + s[t] - v;
        if (i < N) { g_off[i] = excl; g_cur[i] = excl; }
        __syncthreads();
        if (t == 1023) carry_s += s[1023];
        __syncthreads();
    }
    if (t == 0) g_off[N] = carry_s;
}

__global__ void fill_kernel(const void* __restrict__ eidx, int E) {
    int e = blockIdx.x * blockDim.x + threadIdx.x;
    if (e >= E) return;
    int src, dst;
    if (g_is64) {
        const long long* p = (const long long*)eidx;
        src = (int)p[e];
        dst = (int)p[(size_t)E + e];
    } else {
        const int* p = (const int*)eidx;
        src = p[e];
        dst = p[E + e];
    }
    int pos = atomicAdd(&g_cur[dst], 1);
    g_esrc[pos] = src;
}

// ---------------- gather: agg[n] = sum x[src] (2 threads per node, 20 cols each) ----
__global__ void gather_kernel(int N) {
    int idx = blockIdx.x * blockDim.x + threadIdx.x;
    int node = idx >> 1;
    int half = idx & 1;
    if (node >= N) return;
    int beg = g_off[node], end = g_off[node + 1];
    float4 acc[5];
#pragma unroll
    for (int i = 0; i < 5; i++) acc[i] = make_float4(0.f, 0.f, 0.f, 0.f);

    int e = beg;
    for (; e + 1 < end; e += 2) {
        int s0 = g_esrc[e], s1 = g_esrc[e + 1];
        const float4* x0 = (const float4*)(g_xc + (size_t)s0 * 80 + 40 + half * 20);
        const float4* x1 = (const float4*)(g_xc + (size_t)s1 * 80 + 40 + half * 20);
        float4 v0[5], v1[5];
#pragma unroll
        for (int i = 0; i < 5; i++) v0[i] = x0[i];
#pragma unroll
        for (int i = 0; i < 5; i++) v1[i] = x1[i];
#pragma unroll
        for (int i = 0; i < 5; i++) {
            acc[i].x += v0[i].x + v1[i].x;
            acc[i].y += v0[i].y + v1[i].y;
            acc[i].z += v0[i].z + v1[i].z;
            acc[i].w += v0[i].w + v1[i].w;
        }
    }
    if (e < end) {
        int s0 = g_esrc[e];
        const float4* x0 = (const float4*)(g_xc + (size_t)s0 * 80 + 40 + half * 20);
#pragma unroll
        for (int i = 0; i < 5; i++) {
            float4 v = x0[i];
            acc[i].x += v.x; acc[i].y += v.y; acc[i].z += v.z; acc[i].w += v.w;
        }
    }
    float4* dst = (float4*)(g_xc + (size_t)node * 80 + half * 20);
#pragma unroll
    for (int i = 0; i < 5; i++) dst[i] = acc[i];
}

// ---------------- tf32 tensor-core GEMM ----------------
__device__ __forceinline__ void mma_tf32(float c[4], const uint32_t a[4], const uint32_t b[2]) {
    asm volatile(
        "mma.sync.aligned.m16n8k8.row.col.f32.tf32.tf32.f32 "
        "{%0,%1,%2,%3}, {%4,%5,%6,%7}, {%8,%9}, {%0,%1,%2,%3};\n"
        : "+f"(c[0]), "+f"(c[1]), "+f"(c[2]), "+f"(c[3])
        : "r"(a[0]), "r"(a[1]), "r"(a[2]), "r"(a[3]), "r"(b[0]), "r"(b[1]));
}

// FUSE_PRED: instead of storing C, compute out[m] += sum_n lrelu(c+bias)[m,n]*w_pred[n]
template <int FUSE_PRED>
__global__ __launch_bounds__(256, 2)
void gemm_tf32(const float* __restrict__ A, const float* __restrict__ B,
               const float* __restrict__ bias, float* __restrict__ C, int M, int K,
               const float* __restrict__ w_pred, float* __restrict__ out) {
    __shared__ uint32_t As[128][36];
    __shared__ uint32_t Bs[128][36];

    int tid = threadIdx.x;
    int mB = blockIdx.x * 128;
    int nB = blockIdx.y * 128;
    int wid = tid >> 5, lane = tid & 31;
    int wm = wid >> 2;
    int wn = wid & 3;
    int g = lane >> 2, t = lane & 3;

    float c[4][4][4];
#pragma unroll
    for (int i = 0; i < 4; i++)
#pragma unroll
        for (int j = 0; j < 4; j++)
#pragma unroll
            for (int r = 0; r < 4; r++) c[i][j][r] = 0.f;

    for (int k0 = 0; k0 < K; k0 += 32) {
#pragma unroll
        for (int p = 0; p < 4; p++) {
            int lin = tid + p * 256;
            int r = lin >> 3, cq = lin & 7;
            int k = k0 + cq * 4;
            {
                int m = mB + r;
                float4 v = make_float4(0.f, 0.f, 0.f, 0.f);
                if (m < M) {
                    if (k + 3 < K) v = *(const float4*)(A + (size_t)m * K + k);
                    else {
                        if (k + 0 < K) v.x = A[(size_t)m * K + k + 0];
                        if (k + 1 < K) v.y = A[(size_t)m * K + k + 1];
                        if (k + 2 < K) v.z = A[(size_t)m * K + k + 2];
                        if (k + 3 < K) v.w = A[(size_t)m * K + k + 3];
                    }
                }
                uint4 u = make_uint4(f2tf32(v.x), f2tf32(v.y), f2tf32(v.z), f2tf32(v.w));
                *(uint4*)&As[r][cq * 4] = u;
            }
            {
                int n = nB + r;
                float4 v = make_float4(0.f, 0.f, 0.f, 0.f);
                if (k + 3 < K) v = *(const float4*)(B + (size_t)n * K + k);
                else {
                    if (k + 0 < K) v.x = B[(size_t)n * K + k + 0];
                    if (k + 1 < K) v.y = B[(size_t)n * K + k + 1];
                    if (k + 2 < K) v.z = B[(size_t)n * K + k + 2];
                    if (k + 3 < K) v.w = B[(size_t)n * K + k + 3];
                }
                uint4 u = make_uint4(f2tf32(v.x), f2tf32(v.y), f2tf32(v.z), f2tf32(v.w));
                *(uint4*)&Bs[r][cq * 4] = u;
            }
        }
        __syncthreads();

#pragma unroll
        for (int kk = 0; kk < 32; kk += 8) {
            uint32_t a[4][4], b[4][2];
#pragma unroll
            for (int mt = 0; mt < 4; mt++) {
                int m = wm * 64 + mt * 16 + g;
                a[mt][0] = As[m][kk + t];
                a[mt][1] = As[m + 8][kk + t];
                a[mt][2] = As[m][kk + t + 4];
                a[mt][3] = As[m + 8][kk + t + 4];
            }
#pragma unroll
            for (int nt = 0; nt < 4; nt++) {
                int n = wn * 32 + nt * 8 + g;
                b[nt][0] = Bs[n][kk + t];
                b[nt][1] = Bs[n][kk + t + 4];
            }
#pragma unroll
            for (int mt = 0; mt < 4; mt++)
#pragma unroll
                for (int nt = 0; nt < 4; nt++) mma_tf32(c[mt][nt], a[mt], b[nt]);
        }
        __syncthreads();
    }

#pragma unroll
    for (int mt = 0; mt < 4; mt++) {
        int m0 = mB + wm * 64 + mt * 16 + g;
        float d0 = 0.f, d1 = 0.f;  // fused-pred partial dots for rows m0, m0+8
#pragma unroll
        for (int nt = 0; nt < 4; nt++) {
            int n0 = nB + wn * 32 + nt * 8 + 2 * t;
            float bx = bias[n0], by = bias[n0 + 1];
            float v0x = lrelu(c[mt][nt][0] + bx);
            float v0y = lrelu(c[mt][nt][1] + by);
            float v1x = lrelu(c[mt][nt][2] + bx);
            float v1y = lrelu(c[mt][nt][3] + by);
            if (FUSE_PRED) {
                float wx = w_pred[n0], wy = w_pred[n0 + 1];
                d0 += v0x * wx + v0y * wy;
                d1 += v1x * wx + v1y * wy;
            } else {
                if (m0 < M)     *(float2*)(C + (size_t)m0 * 256 + n0) = make_float2(v0x, v0y);
                if (m0 + 8 < M) *(float2*)(C + (size_t)(m0 + 8) * 256 + n0) = make_float2(v1x, v1y);
            }
        }
        if (FUSE_PRED) {
            // reduce over the 4 lanes sharing g (lanes g*4 + t, t=0..3)
            d0 += __shfl_xor_sync(0xffffffffu, d0, 1);
            d0 += __shfl_xor_sync(0xffffffffu, d0, 2);
            d1 += __shfl_xor_sync(0xffffffffu, d1, 1);
            d1 += __shfl_xor_sync(0xffffffffu, d1, 2);
            if (t == 0) {
                if (m0 < M)     atomicAdd(out + m0, d0);
                if (m0 + 8 < M) atomicAdd(out + m0 + 8, d1);
            }
        }
    }
}

// ---------------- out init: out[m] = b_pred[0] ----------------
__global__ void out_init_kernel(float* __restrict__ out, const float* __restrict__ b, int M) {
    int i = blockIdx.x * blockDim.x + threadIdx.x;
    if (i < M) out[i] = b[0];
}

extern "C" void kernel_launch(void* const* d_in, const int* in_sizes, int n_in,
                              void* d_out, int out_size) {
    const float* pose   = (const float*)d_in[0];
    const float* views  = (const float*)d_in[1];
    const void*  eidx   = d_in[2];
    const float* w_e1   = (const float*)d_in[3];
    const float* b_e1   = (const float*)d_in[4];
    const float* w_e2   = (const float*)d_in[5];
    const float* b_e2   = (const float*)d_in[6];
    const float* w_rel  = (const float*)d_in[7];
    const float* b_rel  = (const float*)d_in[8];
    const float* w_root = (const float*)d_in[9];
    const float* w_l1   = (const float*)d_in[10];
    const float* b_l1   = (const float*)d_in[11];
    const float* w_l2   = (const float*)d_in[12];
    const float* b_l2   = (const float*)d_in[13];
    const float* w_l3   = (const float*)d_in[14];
    const float* b_l3   = (const float*)d_in[15];
    const float* w_pred = (const float*)d_in[16];
    const float* b_pred = (const float*)d_in[17];
    float* out = (float*)d_out;

    int N = in_sizes[0] / 3;
    int E = in_sizes[2] / 2;

    float *xc, *w1, *h0, *h1;
    cudaGetSymbolAddress((void**)&xc, g_xc);
    cudaGetSymbolAddress((void**)&w1, g_w1cat);
    cudaGetSymbolAddress((void**)&h0, g_h0);
    cudaGetSymbolAddress((void**)&h1, g_h1);
    int* cnt;
    cudaGetSymbolAddress((void**)&cnt, g_cnt);

    encoder_kernel<<<(N + 255) / 256, 256>>>(pose, views, w_e1, b_e1, w_e2, b_e2, N);
    pack_w1<<<(256 * 80 + 255) / 256, 256>>>(w_rel, w_root);
    detect_kernel<<<1, 32>>>((const unsigned*)eidx);

    cudaMemsetAsync(cnt, 0, (size_t)N * sizeof(int));
    count_kernel<<<(E + 255) / 256, 256>>>(eidx, E);
    scan_kernel<<<1, 1024>>>(N);
    fill_kernel<<<(E + 255) / 256, 256>>>(eidx, E);
    gather_kernel<<<(2 * N + 255) / 256, 256>>>(N);

    dim3 ggrid((N + 127) / 128, 2);
    gemm_tf32<0><<<ggrid, 256>>>(xc, w1, b_rel, h0, N, 80, nullptr, nullptr);
    gemm_tf32<0><<<ggrid, 256>>>(h0, w_l1, b_l1, h1, N, 256, nullptr, nullptr);
    gemm_tf32<0><<<ggrid, 256>>>(h1, w_l2, b_l2, h0, N, 256, nullptr, nullptr);
    out_init_kernel<<<(N + 255) / 256, 256>>>(out, b_pred, N);
    gemm_tf32<1><<<ggrid, 256>>>(h0, w_l3, b_l3, nullptr, N, 256, w_pred, out);
}

// round 7
// speedup vs baseline: 2.1278x; 1.2641x over previous
#include <cuda_runtime.h>
#include <cstdint>

#define NEG_SLOPE 0.1f
__device__ __forceinline__ float lrelu(float v) { return v >= 0.f ? v : NEG_SLOPE * v; }

// ---------------- static scratch ----------------
#define MAXN 50176
#define MAXE 5000000
__device__ __align__(16) float g_xc[MAXN * 80];     // [N,80]: 0..39 agg, 40..79 x (tf32-rounded)
__device__ __align__(16) float g_w1cat[256 * 80];   // [256,80] = [w_rel|w_root] tf32-rounded
__device__ __align__(16) float g_wl[3 * 256 * 256]; // w_l1,w_l2,w_l3 tf32-rounded
__device__ __align__(16) float g_h0[MAXN * 256];
__device__ __align__(16) float g_h1[MAXN * 256];
__device__ int g_cnt[MAXN];
__device__ int g_off[MAXN + 1];
__device__ int g_cur[MAXN];
__device__ int g_esrc[MAXE];
__device__ int g_bsum[64];
__device__ int g_bbase[64];

__device__ __forceinline__ uint32_t f2tf32(float f) {
    uint32_t r;
    asm("cvt.rna.tf32.f32 %0, %1;" : "=r"(r) : "f"(f));
    return r;
}
__device__ __forceinline__ float tfr(float f) { return __uint_as_float(f2tf32(f)); }

// per-block int64-vs-int32 detection for edge_index (values < 2^31 -> odd words all 0)
__device__ __forceinline__ int block_is64(const unsigned* p, long long nwords) {
    int t = threadIdx.x;
    int odd = 0;
    if (t < 256 && (2 * t + 1) < nwords) odd = (p[2 * t + 1] != 0u);
    return !__syncthreads_or(odd);
}

// ================= fused front: count | encoder | pack+round | out_init =================
__global__ void fused_front(const void* __restrict__ eidx, int E,
                            const float* __restrict__ pose, const float* __restrict__ views,
                            const float* __restrict__ w_e1, const float* __restrict__ b_e1,
                            const float* __restrict__ w_e2, const float* __restrict__ b_e2,
                            const float* __restrict__ w_rel, const float* __restrict__ w_root,
                            const float* __restrict__ w_l1, const float* __restrict__ w_l2,
                            const float* __restrict__ w_l3,
                            const float* __restrict__ b_pred, float* __restrict__ out,
                            int N, int nbCnt, int nbEnc, int nbPack, int nbRnd) {
    int bx = blockIdx.x;
    int t = threadIdx.x;

    if (bx < nbCnt) {
        // ---- count: 4 edges per thread ----
        int is64 = block_is64((const unsigned*)eidx, 2LL * E * 2);
        int base = bx * 1024;
#pragma unroll
        for (int j = 0; j < 4; j++) {
            int e = base + t + j * 256;
            if (e < E) {
                int dst;
                if (is64) dst = (int)((const long long*)eidx)[(size_t)E + e];
                else      dst = ((const int*)eidx)[E + e];
                atomicAdd(&g_cnt[dst], 1);
            }
        }
        return;
    }
    bx -= nbCnt;

    if (bx < nbEnc) {
        // ---- encoder ----
        __shared__ float sw1[81], sb1[9], sw2[27], sb2;
        if (t < 81) sw1[t] = w_e1[t];
        if (t < 9)  sb1[t] = b_e1[t];
        if (t >= 96 && t < 123) sw2[t - 96] = w_e2[t - 96];
        if (t == 127) sb2 = b_e2[0];
        __syncthreads();

        int n = bx * 256 + t;
        if (n >= N) return;

        float* xo = g_xc + (size_t)n * 80 + 40;
        xo[0] = tfr(pose[n * 3 + 0]);
        xo[1] = tfr(pose[n * 3 + 1]);
        xo[2] = tfr(pose[n * 3 + 2]);

        const float* vin = views + (size_t)n * 453;

        float cur[9];
        {
            float in[3][3];
#pragma unroll
            for (int ci = 0; ci < 3; ci++)
#pragma unroll
                for (int k = 0; k < 3; k++) in[ci][k] = vin[ci * 151 + k];
#pragma unroll
            for (int c1 = 0; c1 < 9; c1++) {
                float a = sb1[c1];
#pragma unroll
                for (int ci = 0; ci < 3; ci++)
#pragma unroll
                    for (int k = 0; k < 3; k++) a += sw1[c1 * 9 + ci * 3 + k] * in[ci][k];
                cur[c1] = lrelu(a);
            }
        }
        for (int tt = 0; tt < 37; tt++) {
            float b9[9], c9[9];
#pragma unroll
            for (int which = 0; which < 2; which++) {
                int pos = 2 * tt + 1 + which;
                float in[3][3];
#pragma unroll
                for (int ci = 0; ci < 3; ci++)
#pragma unroll
                    for (int k = 0; k < 3; k++) in[ci][k] = vin[ci * 151 + 2 * pos + k];
                float* dst = which == 0 ? b9 : c9;
#pragma unroll
                for (int c1 = 0; c1 < 9; c1++) {
                    float a = sb1[c1];
#pragma unroll
                    for (int ci = 0; ci < 3; ci++)
#pragma unroll
                        for (int k = 0; k < 3; k++) a += sw1[c1 * 9 + ci * 3 + k] * in[ci][k];
                    dst[c1] = lrelu(a);
                }
            }
            float acc = sb2;
#pragma unroll
            for (int c1 = 0; c1 < 9; c1++)
                acc += cur[c1] * sw2[c1 * 3 + 0] + b9[c1] * sw2[c1 * 3 + 1] + c9[c1] * sw2[c1 * 3 + 2];
            xo[3 + tt] = tfr(lrelu(acc));
#pragma unroll
            for (int c1 = 0; c1 < 9; c1++) cur[c1] = c9[c1];
        }
        return;
    }
    bx -= nbEnc;

    if (bx < nbPack) {
        int i = bx * 256 + t;
        if (i < 256 * 80) {
            int n = i / 80, j = i % 80;
            g_w1cat[i] = tfr((j < 40) ? w_rel[n * 40 + j] : w_root[n * 40 + j - 40]);
        }
        return;
    }
    bx -= nbPack;

    if (bx < nbRnd) {
        int i = bx * 256 + t;
        if (i < 3 * 65536) {
            int which = i >> 16;
            const float* w = which == 0 ? w_l1 : (which == 1 ? w_l2 : w_l3);
            g_wl[i] = tfr(w[i & 65535]);
        }
        return;
    }
    bx -= nbRnd;

    {   // out_init: out[m] = b_pred[0]
        int i = bx * 256 + t;
        if (i < N) out[i] = b_pred[0];
    }
}

// ================= scan (3 kernels) =================
__device__ __forceinline__ int block_incl_scan(int v) {
    __shared__ int ws[32];
    int lane = threadIdx.x & 31, wid = threadIdx.x >> 5;
    int x = v;
#pragma unroll
    for (int o = 1; o < 32; o <<= 1) {
        int y = __shfl_up_sync(0xffffffffu, x, o);
        if (lane >= o) x += y;
    }
    if (lane == 31) ws[wid] = x;
    __syncthreads();
    if (wid == 0) {
        int s = ws[lane];
#pragma unroll
        for (int o = 1; o < 32; o <<= 1) {
            int y = __shfl_up_sync(0xffffffffu, s, o);
            if (lane >= o) s += y;
        }
        ws[lane] = s;
    }
    __syncthreads();
    int base = (wid > 0) ? ws[wid - 1] : 0;
    return base + x;
}

__global__ void scan_a(int N) {
    int i = blockIdx.x * 1024 + threadIdx.x;
    int v = (i < N) ? g_cnt[i] : 0;
    int incl = block_incl_scan(v);
    if (threadIdx.x == 1023) g_bsum[blockIdx.x] = incl;
}
__global__ void scan_b(int nblk) {
    int t = threadIdx.x;
    int v = (t < nblk) ? g_bsum[t] : 0;
    int incl = block_incl_scan(v);
    if (t < nblk) g_bbase[t] = incl - v;
}
__global__ void scan_c(int N) {
    int b = blockIdx.x;
    int i = b * 1024 + threadIdx.x;
    int v = (i < N) ? g_cnt[i] : 0;
    int incl = block_incl_scan(v);
    int excl = g_bbase[b] + incl - v;
    if (i < N) { g_off[i] = excl; g_cur[i] = excl; }
    if (i == N - 1) g_off[N] = excl + v;
}

// ================= fill =================
__global__ void fill_kernel(const void* __restrict__ eidx, int E) {
    int is64 = block_is64((const unsigned*)eidx, 2LL * E * 2);
    int base = blockIdx.x * 1024;
    int t = threadIdx.x;
#pragma unroll
    for (int j = 0; j < 4; j++) {
        int e = base + t + j * 256;
        if (e < E) {
            int src, dst;
            if (is64) {
                const long long* p = (const long long*)eidx;
                src = (int)p[e];
                dst = (int)p[(size_t)E + e];
            } else {
                const int* p = (const int*)eidx;
                src = p[e];
                dst = p[E + e];
            }
            int pos = atomicAdd(&g_cur[dst], 1);
            g_esrc[pos] = src;
        }
    }
}

// ================= gather: agg[n] = sum x[src] ================= (tf32-rounded output)
__global__ void gather_kernel(int N) {
    int idx = blockIdx.x * blockDim.x + threadIdx.x;
    int node = idx >> 1;
    int half = idx & 1;
    if (node >= N) return;
    int beg = g_off[node], end = g_off[node + 1];
    float4 acc[5];
#pragma unroll
    for (int i = 0; i < 5; i++) acc[i] = make_float4(0.f, 0.f, 0.f, 0.f);

    int e = beg;
    for (; e + 1 < end; e += 2) {
        int s0 = g_esrc[e], s1 = g_esrc[e + 1];
        const float4* x0 = (const float4*)(g_xc + (size_t)s0 * 80 + 40 + half * 20);
        const float4* x1 = (const float4*)(g_xc + (size_t)s1 * 80 + 40 + half * 20);
        float4 v0[5], v1[5];
#pragma unroll
        for (int i = 0; i < 5; i++) v0[i] = x0[i];
#pragma unroll
        for (int i = 0; i < 5; i++) v1[i] = x1[i];
#pragma unroll
        for (int i = 0; i < 5; i++) {
            acc[i].x += v0[i].x + v1[i].x;
            acc[i].y += v0[i].y + v1[i].y;
            acc[i].z += v0[i].z + v1[i].z;
            acc[i].w += v0[i].w + v1[i].w;
        }
    }
    if (e < end) {
        int s0 = g_esrc[e];
        const float4* x0 = (const float4*)(g_xc + (size_t)s0 * 80 + 40 + half * 20);
#pragma unroll
        for (int i = 0; i < 5; i++) {
            float4 v = x0[i];
            acc[i].x += v.x; acc[i].y += v.y; acc[i].z += v.z; acc[i].w += v.w;
        }
    }
    float4* dst = (float4*)(g_xc + (size_t)node * 80 + half * 20);
#pragma unroll
    for (int i = 0; i < 5; i++)
        dst[i] = make_float4(tfr(acc[i].x), tfr(acc[i].y), tfr(acc[i].z), tfr(acc[i].w));
}

// ================= tf32 GEMM, cp.async double-buffered =================
__device__ __forceinline__ void mma_tf32(float c[4], const uint32_t a[4], const uint32_t b[2]) {
    asm volatile(
        "mma.sync.aligned.m16n8k8.row.col.f32.tf32.tf32.f32 "
        "{%0,%1,%2,%3}, {%4,%5,%6,%7}, {%8,%9}, {%0,%1,%2,%3};\n"
        : "+f"(c[0]), "+f"(c[1]), "+f"(c[2]), "+f"(c[3])
        : "r"(a[0]), "r"(a[1]), "r"(a[2]), "r"(a[3]), "r"(b[0]), "r"(b[1]));
}
__device__ __forceinline__ void cpasync16(uint32_t saddr, const void* g, int sz) {
    asm volatile("cp.async.cg.shared.global [%0], [%1], 16, %2;"
                 :: "r"(saddr), "l"(g), "r"(sz));
}

// stage layout (uint32 words): stage*9216 + {A:0 / B:4608} + r*36 + c
template <int FUSE_PRED>
__global__ __launch_bounds__(256, 2)
void gemm_tf32(const float* __restrict__ A, const float* __restrict__ B,
               const float* __restrict__ bias, float* __restrict__ C, int M, int K,
               const float* __restrict__ w_pred, float* __restrict__ out) {
    extern __shared__ uint32_t sm[];
    uint32_t sbase = (uint32_t)__cvta_generic_to_shared(sm);

    int tid = threadIdx.x;
    int mB = blockIdx.x * 128;
    int nB = blockIdx.y * 128;
    int wid = tid >> 5, lane = tid & 31;
    int wm = wid >> 2, wn = wid & 3;
    int g = lane >> 2, t = lane & 3;

    const int nk = (K + 31) / 32;

    float c[4][4][4];
#pragma unroll
    for (int i = 0; i < 4; i++)
#pragma unroll
        for (int j = 0; j < 4; j++)
#pragma unroll
            for (int r = 0; r < 4; r++) c[i][j][r] = 0.f;

    // chunk loader: 8 cp.asyncs/thread (4 A-groups, 4 B-groups)
    auto load_chunk = [&](int k0, int stage) {
#pragma unroll
        for (int p = 0; p < 4; p++) {
            int lin = tid + p * 256;
            int r = lin >> 3, cq = lin & 7;
            int k = k0 + cq * 4;
            bool kv = (k < K);
            uint32_t so = sbase + ((stage * 9216 + r * 36 + cq * 4) << 2);
            {
                int m = mB + r;
                bool v = kv && (m < M);
                cpasync16(so, v ? (const void*)(A + (size_t)m * K + k) : (const void*)A,
                          v ? 16 : 0);
            }
            {
                int n = nB + r;
                cpasync16(so + (4608 << 2),
                          kv ? (const void*)(B + (size_t)n * K + k) : (const void*)B,
                          kv ? 16 : 0);
            }
        }
        asm volatile("cp.async.commit_group;");
    };

    load_chunk(0, 0);
    for (int i = 0; i < nk; i++) {
        if (i + 1 < nk) {
            load_chunk((i + 1) * 32, (i + 1) & 1);
            asm volatile("cp.async.wait_group 1;");
        } else {
            asm volatile("cp.async.wait_group 0;");
        }
        __syncthreads();

        const uint32_t* As = sm + (i & 1) * 9216;
        const uint32_t* Bs = As + 4608;
#pragma unroll
        for (int kk = 0; kk < 32; kk += 8) {
            uint32_t a[4][4], b[4][2];
#pragma unroll
            for (int mt = 0; mt < 4; mt++) {
                int m = wm * 64 + mt * 16 + g;
                a[mt][0] = As[m * 36 + kk + t];
                a[mt][1] = As[(m + 8) * 36 + kk + t];
                a[mt][2] = As[m * 36 + kk + t + 4];
                a[mt][3] = As[(m + 8) * 36 + kk + t + 4];
            }
#pragma unroll
            for (int nt = 0; nt < 4; nt++) {
                int n = wn * 32 + nt * 8 + g;
                b[nt][0] = Bs[n * 36 + kk + t];
                b[nt][1] = Bs[n * 36 + kk + t + 4];
            }
#pragma unroll
            for (int mt = 0; mt < 4; mt++)
#pragma unroll
                for (int nt = 0; nt < 4; nt++) mma_tf32(c[mt][nt], a[mt], b[nt]);
        }
        __syncthreads();
    }

#pragma unroll
    for (int mt = 0; mt < 4; mt++) {
        int m0 = mB + wm * 64 + mt * 16 + g;
        float d0 = 0.f, d1 = 0.f;
#pragma unroll
        for (int nt = 0; nt < 4; nt++) {
            int n0 = nB + wn * 32 + nt * 8 + 2 * t;
            float bx = bias[n0], by = bias[n0 + 1];
            float v0x = lrelu(c[mt][nt][0] + bx);
            float v0y = lrelu(c[mt][nt][1] + by);
            float v1x = lrelu(c[mt][nt][2] + bx);
            float v1y = lrelu(c[mt][nt][3] + by);
            if (FUSE_PRED) {
                float wx = w_pred[n0], wy = w_pred[n0 + 1];
                d0 += v0x * wx + v0y * wy;
                d1 += v1x * wx + v1y * wy;
            } else {
                // round outputs to tf32 so the next GEMM can skip conversion
                if (m0 < M)
                    *(float2*)(C + (size_t)m0 * 256 + n0) = make_float2(tfr(v0x), tfr(v0y));
                if (m0 + 8 < M)
                    *(float2*)(C + (size_t)(m0 + 8) * 256 + n0) = make_float2(tfr(v1x), tfr(v1y));
            }
        }
        if (FUSE_PRED) {
            d0 += __shfl_xor_sync(0xffffffffu, d0, 1);
            d0 += __shfl_xor_sync(0xffffffffu, d0, 2);
            d1 += __shfl_xor_sync(0xffffffffu, d1, 1);
            d1 += __shfl_xor_sync(0xffffffffu, d1, 2);
            if (t == 0) {
                if (m0 < M)     atomicAdd(out + m0, d0);
                if (m0 + 8 < M) atomicAdd(out + m0 + 8, d1);
            }
        }
    }
}

extern "C" void kernel_launch(void* const* d_in, const int* in_sizes, int n_in,
                              void* d_out, int out_size) {
    const float* pose   = (const float*)d_in[0];
    const float* views  = (const float*)d_in[1];
    const void*  eidx   = d_in[2];
    const float* w_e1   = (const float*)d_in[3];
    const float* b_e1   = (const float*)d_in[4];
    const float* w_e2   = (const float*)d_in[5];
    const float* b_e2   = (const float*)d_in[6];
    const float* w_rel  = (const float*)d_in[7];
    const float* b_rel  = (const float*)d_in[8];
    const float* w_root = (const float*)d_in[9];
    const float* w_l1   = (const float*)d_in[10];
    const float* b_l1   = (const float*)d_in[11];
    const float* w_l2   = (const float*)d_in[12];
    const float* b_l2   = (const float*)d_in[13];
    const float* w_l3   = (const float*)d_in[14];
    const float* b_l3   = (const float*)d_in[15];
    const float* w_pred = (const float*)d_in[16];
    const float* b_pred = (const float*)d_in[17];
    float* out = (float*)d_out;

    int N = in_sizes[0] / 3;
    int E = in_sizes[2] / 2;

    float *xc, *w1, *wl, *h0, *h1;
    cudaGetSymbolAddress((void**)&xc, g_xc);
    cudaGetSymbolAddress((void**)&w1, g_w1cat);
    cudaGetSymbolAddress((void**)&wl, g_wl);
    cudaGetSymbolAddress((void**)&h0, g_h0);
    cudaGetSymbolAddress((void**)&h1, g_h1);
    int* cnt;
    cudaGetSymbolAddress((void**)&cnt, g_cnt);

    const int SMEM = 2 * 9216 * 4;  // 73728 B
    cudaFuncSetAttribute(gemm_tf32<0>, cudaFuncAttributeMaxDynamicSharedMemorySize, SMEM);
    cudaFuncSetAttribute(gemm_tf32<1>, cudaFuncAttributeMaxDynamicSharedMemorySize, SMEM);

    cudaMemsetAsync(cnt, 0, (size_t)N * sizeof(int));

    int nbCnt = (E + 1023) / 1024;
    int nbEnc = (N + 255) / 256;
    int nbPack = (256 * 80 + 255) / 256;
    int nbRnd = (3 * 65536 + 255) / 256;
    int nbOut = (N + 255) / 256;
    fused_front<<<nbCnt + nbEnc + nbPack + nbRnd + nbOut, 256>>>(
        eidx, E, pose, views, w_e1, b_e1, w_e2, b_e2,
        w_rel, w_root, w_l1, w_l2, w_l3, b_pred, out,
        N, nbCnt, nbEnc, nbPack, nbRnd);

    int nblk = (N + 1023) / 1024;
    scan_a<<<nblk, 1024>>>(N);
    scan_b<<<1, 1024>>>(nblk);
    scan_c<<<nblk, 1024>>>(N);

    fill_kernel<<<(E + 1023) / 1024, 256>>>(eidx, E);
    gather_kernel<<<(2 * N + 255) / 256, 256>>>(N);

    dim3 ggrid((N + 127) / 128, 2);
    gemm_tf32<0><<<ggrid, 256, SMEM>>>(xc, w1, b_rel, h0, N, 80, nullptr, nullptr);
    gemm_tf32<0><<<ggrid, 256, SMEM>>>(h0, wl, b_l1, h1, N, 256, nullptr, nullptr);
    gemm_tf32<0><<<ggrid, 256, SMEM>>>(h1, wl + 65536, b_l2, h0, N, 256, nullptr, nullptr);
    gemm_tf32<1><<<ggrid, 256, SMEM>>>(h0, wl + 2 * 65536, b_l3, nullptr, N, 256, w_pred, out);
}

// round 10
// speedup vs baseline: 2.1643x; 1.0171x over previous
#include <cuda_runtime.h>
#include <cstdint>

#define NEG_SLOPE 0.1f
__device__ __forceinline__ float lrelu(float v) { return v >= 0.f ? v : NEG_SLOPE * v; }

// ---------------- static scratch ----------------
#define MAXN 50176
#define MAXE 5000000
__device__ __align__(16) float g_xc[MAXN * 80];     // [N,80]: 0..39 agg, 40..79 x (tf32-rounded)
__device__ __align__(16) float g_w1cat[256 * 80];   // [256,80] = [w_rel|w_root] tf32-rounded
__device__ __align__(16) float g_wl[3 * 256 * 256]; // w_l1,w_l2,w_l3 tf32-rounded
__device__ __align__(16) float g_h0[MAXN * 256];
__device__ __align__(16) float g_h1[MAXN * 256];
__device__ int g_cnt[MAXN];
__device__ int g_off[MAXN + 1];
__device__ int g_cur[MAXN];
__device__ int g_esrc[MAXE];
__device__ int g_bsum[64];
__device__ int g_bbase[64];

__device__ __forceinline__ uint32_t f2tf32(float f) {
    uint32_t r;
    asm("cvt.rna.tf32.f32 %0, %1;" : "=r"(r) : "f"(f));
    return r;
}
__device__ __forceinline__ float tfr(float f) { return __uint_as_float(f2tf32(f)); }

// per-block int64-vs-int32 detection for edge_index (values < 2^31 -> odd words all 0)
__device__ __forceinline__ int block_is64(const unsigned* p, long long nwords) {
    int t = threadIdx.x;
    int odd = 0;
    if (t < 256 && (2 * t + 1) < nwords) odd = (p[2 * t + 1] != 0u);
    return !__syncthreads_or(odd);
}

// ================= fused front: count | encoder | pack+round | out_init =================
__global__ void fused_front(const void* __restrict__ eidx, int E,
                            const float* __restrict__ pose, const float* __restrict__ views,
                            const float* __restrict__ w_e1, const float* __restrict__ b_e1,
                            const float* __restrict__ w_e2, const float* __restrict__ b_e2,
                            const float* __restrict__ w_rel, const float* __restrict__ w_root,
                            const float* __restrict__ w_l1, const float* __restrict__ w_l2,
                            const float* __restrict__ w_l3,
                            const float* __restrict__ b_pred, float* __restrict__ out,
                            int N, int nbCnt, int nbEnc, int nbPack, int nbRnd) {
    int bx = blockIdx.x;
    int t = threadIdx.x;

    if (bx < nbCnt) {
        int is64 = block_is64((const unsigned*)eidx, 2LL * E * 2);
        int base = bx * 1024;
#pragma unroll
        for (int j = 0; j < 4; j++) {
            int e = base + t + j * 256;
            if (e < E) {
                int dst;
                if (is64) dst = (int)((const long long*)eidx)[(size_t)E + e];
                else      dst = ((const int*)eidx)[E + e];
                atomicAdd(&g_cnt[dst], 1);
            }
        }
        return;
    }
    bx -= nbCnt;

    if (bx < nbEnc) {
        __shared__ float sw1[81], sb1[9], sw2[27], sb2;
        if (t < 81) sw1[t] = w_e1[t];
        if (t < 9)  sb1[t] = b_e1[t];
        if (t >= 96 && t < 123) sw2[t - 96] = w_e2[t - 96];
        if (t == 127) sb2 = b_e2[0];
        __syncthreads();

        int n = bx * 256 + t;
        if (n >= N) return;

        float* xo = g_xc + (size_t)n * 80 + 40;
        xo[0] = tfr(pose[n * 3 + 0]);
        xo[1] = tfr(pose[n * 3 + 1]);
        xo[2] = tfr(pose[n * 3 + 2]);

        const float* vin = views + (size_t)n * 453;

        float cur[9];
        {
            float in[3][3];
#pragma unroll
            for (int ci = 0; ci < 3; ci++)
#pragma unroll
                for (int k = 0; k < 3; k++) in[ci][k] = vin[ci * 151 + k];
#pragma unroll
            for (int c1 = 0; c1 < 9; c1++) {
                float a = sb1[c1];
#pragma unroll
                for (int ci = 0; ci < 3; ci++)
#pragma unroll
                    for (int k = 0; k < 3; k++) a += sw1[c1 * 9 + ci * 3 + k] * in[ci][k];
                cur[c1] = lrelu(a);
            }
        }
        for (int tt = 0; tt < 37; tt++) {
            float b9[9], c9[9];
#pragma unroll
            for (int which = 0; which < 2; which++) {
                int pos = 2 * tt + 1 + which;
                float in[3][3];
#pragma unroll
                for (int ci = 0; ci < 3; ci++)
#pragma unroll
                    for (int k = 0; k < 3; k++) in[ci][k] = vin[ci * 151 + 2 * pos + k];
                float* dst = which == 0 ? b9 : c9;
#pragma unroll
                for (int c1 = 0; c1 < 9; c1++) {
                    float a = sb1[c1];
#pragma unroll
                    for (int ci = 0; ci < 3; ci++)
#pragma unroll
                        for (int k = 0; k < 3; k++) a += sw1[c1 * 9 + ci * 3 + k] * in[ci][k];
                    dst[c1] = lrelu(a);
                }
            }
            float acc = sb2;
#pragma unroll
            for (int c1 = 0; c1 < 9; c1++)
                acc += cur[c1] * sw2[c1 * 3 + 0] + b9[c1] * sw2[c1 * 3 + 1] + c9[c1] * sw2[c1 * 3 + 2];
            xo[3 + tt] = tfr(lrelu(acc));
#pragma unroll
            for (int c1 = 0; c1 < 9; c1++) cur[c1] = c9[c1];
        }
        return;
    }
    bx -= nbEnc;

    if (bx < nbPack) {
        int i = bx * 256 + t;
        if (i < 256 * 80) {
            int n = i / 80, j = i % 80;
            g_w1cat[i] = tfr((j < 40) ? w_rel[n * 40 + j] : w_root[n * 40 + j - 40]);
        }
        return;
    }
    bx -= nbPack;

    if (bx < nbRnd) {
        int i = bx * 256 + t;
        if (i < 3 * 65536) {
            int which = i >> 16;
            const float* w = which == 0 ? w_l1 : (which == 1 ? w_l2 : w_l3);
            g_wl[i] = tfr(w[i & 65535]);
        }
        return;
    }
    bx -= nbRnd;

    {
        int i = bx * 256 + t;
        if (i < N) out[i] = b_pred[0];
    }
}

// ================= scan (3 kernels) =================
__device__ __forceinline__ int block_incl_scan(int v) {
    __shared__ int ws[32];
    int lane = threadIdx.x & 31, wid = threadIdx.x >> 5;
    int x = v;
#pragma unroll
    for (int o = 1; o < 32; o <<= 1) {
        int y = __shfl_up_sync(0xffffffffu, x, o);
        if (lane >= o) x += y;
    }
    if (lane == 31) ws[wid] = x;
    __syncthreads();
    if (wid == 0) {
        int s = ws[lane];
#pragma unroll
        for (int o = 1; o < 32; o <<= 1) {
            int y = __shfl_up_sync(0xffffffffu, s, o);
            if (lane >= o) s += y;
        }
        ws[lane] = s;
    }
    __syncthreads();
    int base = (wid > 0) ? ws[wid - 1] : 0;
    return base + x;
}

__global__ void scan_a(int N) {
    int i = blockIdx.x * 1024 + threadIdx.x;
    int v = (i < N) ? g_cnt[i] : 0;
    int incl = block_incl_scan(v);
    if (threadIdx.x == 1023) g_bsum[blockIdx.x] = incl;
}
__global__ void scan_b(int nblk) {
    int t = threadIdx.x;
    int v = (t < nblk) ? g_bsum[t] : 0;
    int incl = block_incl_scan(v);
    if (t < nblk) g_bbase[t] = incl - v;
}
__global__ void scan_c(int N) {
    int b = blockIdx.x;
    int i = b * 1024 + threadIdx.x;
    int v = (i < N) ? g_cnt[i] : 0;
    int incl = block_incl_scan(v);
    int excl = g_bbase[b] + incl - v;
    if (i < N) { g_off[i] = excl; g_cur[i] = excl; }
    if (i == N - 1) g_off[N] = excl + v;
}

// ================= fill =================
__global__ void fill_kernel(const void* __restrict__ eidx, int E) {
    int is64 = block_is64((const unsigned*)eidx, 2LL * E * 2);
    int base = blockIdx.x * 1024;
    int t = threadIdx.x;
#pragma unroll
    for (int j = 0; j < 4; j++) {
        int e = base + t + j * 256;
        if (e < E) {
            int src, dst;
            if (is64) {
                const long long* p = (const long long*)eidx;
                src = (int)p[e];
                dst = (int)p[(size_t)E + e];
            } else {
                const int* p = (const int*)eidx;
                src = p[e];
                dst = p[E + e];
            }
            int pos = atomicAdd(&g_cur[dst], 1);
            g_esrc[pos] = src;
        }
    }
}

// ================= gather: agg[n] = sum x[src] ================= (tf32-rounded output)
__global__ void gather_kernel(int N) {
    int idx = blockIdx.x * blockDim.x + threadIdx.x;
    int node = idx >> 1;
    int half = idx & 1;
    if (node >= N) return;
    int beg = g_off[node], end = g_off[node + 1];
    float4 acc[5];
#pragma unroll
    for (int i = 0; i < 5; i++) acc[i] = make_float4(0.f, 0.f, 0.f, 0.f);

    int e = beg;
    for (; e + 1 < end; e += 2) {
        int s0 = g_esrc[e], s1 = g_esrc[e + 1];
        const float4* x0 = (const float4*)(g_xc + (size_t)s0 * 80 + 40 + half * 20);
        const float4* x1 = (const float4*)(g_xc + (size_t)s1 * 80 + 40 + half * 20);
        float4 v0[5], v1[5];
#pragma unroll
        for (int i = 0; i < 5; i++) v0[i] = x0[i];
#pragma unroll
        for (int i = 0; i < 5; i++) v1[i] = x1[i];
#pragma unroll
        for (int i = 0; i < 5; i++) {
            acc[i].x += v0[i].x + v1[i].x;
            acc[i].y += v0[i].y + v1[i].y;
            acc[i].z += v0[i].z + v1[i].z;
            acc[i].w += v0[i].w + v1[i].w;
        }
    }
    if (e < end) {
        int s0 = g_esrc[e];
        const float4* x0 = (const float4*)(g_xc + (size_t)s0 * 80 + 40 + half * 20);
#pragma unroll
        for (int i = 0; i < 5; i++) {
            float4 v = x0[i];
            acc[i].x += v.x; acc[i].y += v.y; acc[i].z += v.z; acc[i].w += v.w;
        }
    }
    float4* dst = (float4*)(g_xc + (size_t)node * 80 + half * 20);
#pragma unroll
    for (int i = 0; i < 5; i++)
        dst[i] = make_float4(tfr(acc[i].x), tfr(acc[i].y), tfr(acc[i].z), tfr(acc[i].w));
}

// ================= tf32 GEMM, XOR-swizzled smem, 3-stage cp.async =================
// smem word layout per stage: A at 0 (128 rows x 32 words), B at 4096.
// word addr = row*32 + (k ^ ((row&7)<<2))  -> bank = k ^ (g<<2): conflict-free for
// both cp.async writes (16B blocks stay contiguous) and fragment LDS (all 32 lanes
// distinct banks, since every row this thread touches has row&7 == g).
__device__ __forceinline__ void mma_tf32(float c[4], const uint32_t a[4], const uint32_t b[2]) {
    asm volatile(
        "mma.sync.aligned.m16n8k8.row.col.f32.tf32.tf32.f32 "
        "{%0,%1,%2,%3}, {%4,%5,%6,%7}, {%8,%9}, {%0,%1,%2,%3};\n"
        : "+f"(c[0]), "+f"(c[1]), "+f"(c[2]), "+f"(c[3])
        : "r"(a[0]), "r"(a[1]), "r"(a[2]), "r"(a[3]), "r"(b[0]), "r"(b[1]));
}
__device__ __forceinline__ void cpasync16(uint32_t saddr, const void* g, int sz) {
    asm volatile("cp.async.cg.shared.global [%0], [%1], 16, %2;"
                 :: "r"(saddr), "l"(g), "r"(sz));
}

#define STAGE_WORDS 8192
#define NSTAGE 3

template <int FUSE_PRED>
__global__ __launch_bounds__(256, 2)
void gemm_tf32(const float* __restrict__ A, const float* __restrict__ B,
               const float* __restrict__ bias, float* __restrict__ C, int M, int K,
               const float* __restrict__ w_pred, float* __restrict__ out) {
    extern __shared__ uint32_t sm[];
    uint32_t sbase = (uint32_t)__cvta_generic_to_shared(sm);

    int tid = threadIdx.x;
    int mB = blockIdx.x * 128;
    int nB = blockIdx.y * 128;
    int wid = tid >> 5, lane = tid & 31;
    int wm = wid >> 2, wn = wid & 3;
    int g = lane >> 2, t = lane & 3;
    int xg = g << 2;  // per-thread swizzle constant

    const int nk = (K + 31) / 32;

    float c[4][4][4];
#pragma unroll
    for (int i = 0; i < 4; i++)
#pragma unroll
        for (int j = 0; j < 4; j++)
#pragma unroll
            for (int r = 0; r < 4; r++) c[i][j][r] = 0.f;

    auto load_chunk = [&](int k0, int stage) {
#pragma unroll
        for (int p = 0; p < 4; p++) {
            int lin = tid + p * 256;
            int r = lin >> 3, cq = lin & 7;
            int k = k0 + cq * 4;
            bool kv = (k < K);
            int swc = (cq * 4) ^ ((r & 7) << 2);
            uint32_t so = sbase + ((stage * STAGE_WORDS + r * 32 + swc) << 2);
            {
                int m = mB + r;
                bool v = kv && (m < M);
                cpasync16(so, v ? (const void*)(A + (size_t)m * K + k) : (const void*)A,
                          v ? 16 : 0);
            }
            {
                int n = nB + r;
                cpasync16(so + (4096 << 2),
                          kv ? (const void*)(B + (size_t)n * K + k) : (const void*)B,
                          kv ? 16 : 0);
            }
        }
        asm volatile("cp.async.commit_group;");
    };

    load_chunk(0, 0);
    if (nk > 1) load_chunk(32, 1);

    for (int i = 0; i < nk; i++) {
        if (i + 2 < nk) {
            load_chunk((i + 2) * 32, (i + 2) % NSTAGE);
            asm volatile("cp.async.wait_group 2;");
        } else if (i + 1 < nk) {
            asm volatile("cp.async.wait_group 1;");
        } else {
            asm volatile("cp.async.wait_group 0;");
        }
        __syncthreads();

        const uint32_t* As = sm + (i % NSTAGE) * STAGE_WORDS;
        const uint32_t* Bs = As + 4096;
#pragma unroll
        for (int kk = 0; kk < 32; kk += 8) {
            int c0 = (kk + t) ^ xg;
            int c1 = (kk + t + 4) ^ xg;
            uint32_t a[4][4], b[4][2];
#pragma unroll
            for (int mt = 0; mt < 4; mt++) {
                int m = wm * 64 + mt * 16 + g;
                a[mt][0] = As[m * 32 + c0];
                a[mt][1] = As[(m + 8) * 32 + c0];
                a[mt][2] = As[m * 32 + c1];
                a[mt][3] = As[(m + 8) * 32 + c1];
            }
#pragma unroll
            for (int nt = 0; nt < 4; nt++) {
                int n = wn * 32 + nt * 8 + g;
                b[nt][0] = Bs[n * 32 + c0];
                b[nt][1] = Bs[n * 32 + c1];
            }
#pragma unroll
            for (int mt = 0; mt < 4; mt++)
#pragma unroll
                for (int nt = 0; nt < 4; nt++) mma_tf32(c[mt][nt], a[mt], b[nt]);
        }
        __syncthreads();
    }

#pragma unroll
    for (int mt = 0; mt < 4; mt++) {
        int m0 = mB + wm * 64 + mt * 16 + g;
        float d0 = 0.f, d1 = 0.f;
#pragma unroll
        for (int nt = 0; nt < 4; nt++) {
            int n0 = nB + wn * 32 + nt * 8 + 2 * t;
            float bx = bias[n0], by = bias[n0 + 1];
            float v0x = lrelu(c[mt][nt][0] + bx);
            float v0y = lrelu(c[mt][nt][1] + by);
            float v1x = lrelu(c[mt][nt][2] + bx);
            float v1y = lrelu(c[mt][nt][3] + by);
            if (FUSE_PRED) {
                float wx = w_pred[n0], wy = w_pred[n0 + 1];
                d0 += v0x * wx + v0y * wy;
                d1 += v1x * wx + v1y * wy;
            } else {
                if (m0 < M)
                    *(float2*)(C + (size_t)m0 * 256 + n0) = make_float2(tfr(v0x), tfr(v0y));
                if (m0 + 8 < M)
                    *(float2*)(C + (size_t)(m0 + 8) * 256 + n0) = make_float2(tfr(v1x), tfr(v1y));
            }
        }
        if (FUSE_PRED) {
            d0 += __shfl_xor_sync(0xffffffffu, d0, 1);
            d0 += __shfl_xor_sync(0xffffffffu, d0, 2);
            d1 += __shfl_xor_sync(0xffffffffu, d1, 1);
            d1 += __shfl_xor_sync(0xffffffffu, d1, 2);
            if (t == 0) {
                if (m0 < M)     atomicAdd(out + m0, d0);
                if (m0 + 8 < M) atomicAdd(out + m0 + 8, d1);
            }
        }
    }
}

extern "C" void kernel_launch(void* const* d_in, const int* in_sizes, int n_in,
                              void* d_out, int out_size) {
    const float* pose   = (const float*)d_in[0];
    const float* views  = (const float*)d_in[1];
    const void*  eidx   = d_in[2];
    const float* w_e1   = (const float*)d_in[3];
    const float* b_e1   = (const float*)d_in[4];
    const float* w_e2   = (const float*)d_in[5];
    const float* b_e2   = (const float*)d_in[6];
    const float* w_rel  = (const float*)d_in[7];
    const float* b_rel  = (const float*)d_in[8];
    const float* w_root = (const float*)d_in[9];
    const float* w_l1   = (const float*)d_in[10];
    const float* b_l1   = (const float*)d_in[11];
    const float* w_l2   = (const float*)d_in[12];
    const float* b_l2   = (const float*)d_in[13];
    const float* w_l3   = (const float*)d_in[14];
    const float* b_l3   = (const float*)d_in[15];
    const float* w_pred = (const float*)d_in[16];
    const float* b_pred = (const float*)d_in[17];
    float* out = (float*)d_out;

    int N = in_sizes[0] / 3;
    int E = in_sizes[2] / 2;

    float *xc, *w1, *wl, *h0, *h1;
    cudaGetSymbolAddress((void**)&xc, g_xc);
    cudaGetSymbolAddress((void**)&w1, g_w1cat);
    cudaGetSymbolAddress((void**)&wl, g_wl);
    cudaGetSymbolAddress((void**)&h0, g_h0);
    cudaGetSymbolAddress((void**)&h1, g_h1);
    int* cnt;
    cudaGetSymbolAddress((void**)&cnt, g_cnt);

    const int SMEM = NSTAGE * STAGE_WORDS * 4;  // 98304 B
    cudaFuncSetAttribute(gemm_tf32<0>, cudaFuncAttributeMaxDynamicSharedMemorySize, SMEM);
    cudaFuncSetAttribute(gemm_tf32<1>, cudaFuncAttributeMaxDynamicSharedMemorySize, SMEM);

    cudaMemsetAsync(cnt, 0, (size_t)N * sizeof(int));

    int nbCnt = (E + 1023) / 1024;
    int nbEnc = (N + 255) / 256;
    int nbPack = (256 * 80 + 255) / 256;
    int nbRnd = (3 * 65536 + 255) / 256;
    int nbOut = (N + 255) / 256;
    fused_front<<<nbCnt + nbEnc + nbPack + nbRnd + nbOut, 256>>>(
        eidx, E, pose, views, w_e1, b_e1, w_e2, b_e2,
        w_rel, w_root, w_l1, w_l2, w_l3, b_pred, out,
        N, nbCnt, nbEnc, nbPack, nbRnd);

    int nblk = (N + 1023) / 1024;
    scan_a<<<nblk, 1024>>>(N);
    scan_b<<<1, 1024>>>(nblk);
    scan_c<<<nblk, 1024>>>(N);

    fill_kernel<<<(E + 1023) / 1024, 256>>>(eidx, E);
    gather_kernel<<<(2 * N + 255) / 256, 256>>>(N);

    dim3 ggrid((N + 127) / 128, 2);
    gemm_tf32<0><<<ggrid, 256, SMEM>>>(xc, w1, b_rel, h0, N, 80, nullptr, nullptr);
    gemm_tf32<0><<<ggrid, 256, SMEM>>>(h0, wl, b_l1, h1, N, 256, nullptr, nullptr);
    gemm_tf32<0><<<ggrid, 256, SMEM>>>(h1, wl + 65536, b_l2, h0, N, 256, nullptr, nullptr);
    gemm_tf32<1><<<ggrid, 256, SMEM>>>(h0, wl + 2 * 65536, b_l3, nullptr, N, 256, w_pred, out);
}

// round 11
// speedup vs baseline: 2.5794x; 1.1918x over previous
#include <cuda_runtime.h>
#include <cuda_fp16.h>
#include <cstdint>

#define NEG_SLOPE 0.1f
__device__ __forceinline__ float lrelu(float v) { return v >= 0.f ? v : NEG_SLOPE * v; }

// ---------------- static scratch ----------------
#define MAXN 50176
#define MAXE 5000000
__device__ __align__(16) __half g_xc[MAXN * 80];     // [N,80] half: 0..39 agg, 40..79 x
__device__ __align__(16) __half g_w1cat[256 * 80];   // [256,80] = [w_rel|w_root] half
__device__ __align__(16) __half g_wl[3 * 256 * 256]; // w_l1,w_l2,w_l3 half
__device__ __align__(16) __half g_h0[MAXN * 256];
__device__ __align__(16) __half g_h1[MAXN * 256];
__device__ int g_cnt[MAXN];
__device__ int g_off[MAXN + 1];
__device__ int g_cur[MAXN];
__device__ int g_esrc[MAXE];
__device__ int g_bsum[64];
__device__ int g_bbase[64];

// per-block int64-vs-int32 detection for edge_index (values < 2^31 -> odd words all 0)
__device__ __forceinline__ int block_is64(const unsigned* p, long long nwords) {
    int t = threadIdx.x;
    int odd = 0;
    if (t < 256 && (2 * t + 1) < nwords) odd = (p[2 * t + 1] != 0u);
    return !__syncthreads_or(odd);
}

// ================= fused front: count | encoder | pack | out_init =================
__global__ void fused_front(const void* __restrict__ eidx, int E,
                            const float* __restrict__ pose, const float* __restrict__ views,
                            const float* __restrict__ w_e1, const float* __restrict__ b_e1,
                            const float* __restrict__ w_e2, const float* __restrict__ b_e2,
                            const float* __restrict__ w_rel, const float* __restrict__ w_root,
                            const float* __restrict__ w_l1, const float* __restrict__ w_l2,
                            const float* __restrict__ w_l3,
                            const float* __restrict__ b_pred, float* __restrict__ out,
                            int N, int nbCnt, int nbEnc, int nbPack, int nbRnd) {
    int bx = blockIdx.x;
    int t = threadIdx.x;

    if (bx < nbCnt) {
        int is64 = block_is64((const unsigned*)eidx, 2LL * E * 2);
        int base = bx * 1024;
#pragma unroll
        for (int j = 0; j < 4; j++) {
            int e = base + t + j * 256;
            if (e < E) {
                int dst;
                if (is64) dst = (int)((const long long*)eidx)[(size_t)E + e];
                else      dst = ((const int*)eidx)[E + e];
                atomicAdd(&g_cnt[dst], 1);
            }
        }
        return;
    }
    bx -= nbCnt;

    if (bx < nbEnc) {
        __shared__ float sw1[81], sb1[9], sw2[27], sb2;
        if (t < 81) sw1[t] = w_e1[t];
        if (t < 9)  sb1[t] = b_e1[t];
        if (t >= 96 && t < 123) sw2[t - 96] = w_e2[t - 96];
        if (t == 127) sb2 = b_e2[0];
        __syncthreads();

        int n = bx * 256 + t;
        if (n >= N) return;

        __half* xo = g_xc + (size_t)n * 80 + 40;
        xo[0] = __float2half_rn(pose[n * 3 + 0]);
        xo[1] = __float2half_rn(pose[n * 3 + 1]);
        xo[2] = __float2half_rn(pose[n * 3 + 2]);

        const float* vin = views + (size_t)n * 453;

        float cur[9];
        {
            float in[3][3];
#pragma unroll
            for (int ci = 0; ci < 3; ci++)
#pragma unroll
                for (int k = 0; k < 3; k++) in[ci][k] = vin[ci * 151 + k];
#pragma unroll
            for (int c1 = 0; c1 < 9; c1++) {
                float a = sb1[c1];
#pragma unroll
                for (int ci = 0; ci < 3; ci++)
#pragma unroll
                    for (int k = 0; k < 3; k++) a += sw1[c1 * 9 + ci * 3 + k] * in[ci][k];
                cur[c1] = lrelu(a);
            }
        }
        for (int tt = 0; tt < 37; tt++) {
            float b9[9], c9[9];
#pragma unroll
            for (int which = 0; which < 2; which++) {
                int pos = 2 * tt + 1 + which;
                float in[3][3];
#pragma unroll
                for (int ci = 0; ci < 3; ci++)
#pragma unroll
                    for (int k = 0; k < 3; k++) in[ci][k] = vin[ci * 151 + 2 * pos + k];
                float* dst = which == 0 ? b9 : c9;
#pragma unroll
                for (int c1 = 0; c1 < 9; c1++) {
                    float a = sb1[c1];
#pragma unroll
                    for (int ci = 0; ci < 3; ci++)
#pragma unroll
                        for (int k = 0; k < 3; k++) a += sw1[c1 * 9 + ci * 3 + k] * in[ci][k];
                    dst[c1] = lrelu(a);
                }
            }
            float acc = sb2;
#pragma unroll
            for (int c1 = 0; c1 < 9; c1++)
                acc += cur[c1] * sw2[c1 * 3 + 0] + b9[c1] * sw2[c1 * 3 + 1] + c9[c1] * sw2[c1 * 3 + 2];
            xo[3 + tt] = __float2half_rn(lrelu(acc));
#pragma unroll
            for (int c1 = 0; c1 < 9; c1++) cur[c1] = c9[c1];
        }
        return;
    }
    bx -= nbEnc;

    if (bx < nbPack) {
        int i = bx * 256 + t;
        if (i < 256 * 80) {
            int n = i / 80, j = i % 80;
            g_w1cat[i] = __float2half_rn((j < 40) ? w_rel[n * 40 + j] : w_root[n * 40 + j - 40]);
        }
        return;
    }
    bx -= nbPack;

    if (bx < nbRnd) {
        int i = bx * 256 + t;
        if (i < 3 * 65536) {
            int which = i >> 16;
            const float* w = which == 0 ? w_l1 : (which == 1 ? w_l2 : w_l3);
            g_wl[i] = __float2half_rn(w[i & 65535]);
        }
        return;
    }
    bx -= nbRnd;

    {
        int i = bx * 256 + t;
        if (i < N) out[i] = b_pred[0];
    }
}

// ================= scan (3 kernels) =================
__device__ __forceinline__ int block_incl_scan(int v) {
    __shared__ int ws[32];
    int lane = threadIdx.x & 31, wid = threadIdx.x >> 5;
    int x = v;
#pragma unroll
    for (int o = 1; o < 32; o <<= 1) {
        int y = __shfl_up_sync(0xffffffffu, x, o);
        if (lane >= o) x += y;
    }
    if (lane == 31) ws[wid] = x;
    __syncthreads();
    if (wid == 0) {
        int s = ws[lane];
#pragma unroll
        for (int o = 1; o < 32; o <<= 1) {
            int y = __shfl_up_sync(0xffffffffu, s, o);
            if (lane >= o) s += y;
        }
        ws[lane] = s;
    }
    __syncthreads();
    int base = (wid > 0) ? ws[wid - 1] : 0;
    return base + x;
}

__global__ void scan_a(int N) {
    int i = blockIdx.x * 1024 + threadIdx.x;
    int v = (i < N) ? g_cnt[i] : 0;
    int incl = block_incl_scan(v);
    if (threadIdx.x == 1023) g_bsum[blockIdx.x] = incl;
}
__global__ void scan_b(int nblk) {
    int t = threadIdx.x;
    int v = (t < nblk) ? g_bsum[t] : 0;
    int incl = block_incl_scan(v);
    if (t < nblk) g_bbase[t] = incl - v;
}
__global__ void scan_c(int N) {
    int b = blockIdx.x;
    int i = b * 1024 + threadIdx.x;
    int v = (i < N) ? g_cnt[i] : 0;
    int incl = block_incl_scan(v);
    int excl = g_bbase[b] + incl - v;
    if (i < N) { g_off[i] = excl; g_cur[i] = excl; }
    if (i == N - 1) g_off[N] = excl + v;
}

// ================= fill =================
__global__ void fill_kernel(const void* __restrict__ eidx, int E) {
    int is64 = block_is64((const unsigned*)eidx, 2LL * E * 2);
    int base = blockIdx.x * 1024;
    int t = threadIdx.x;
#pragma unroll
    for (int j = 0; j < 4; j++) {
        int e = base + t + j * 256;
        if (e < E) {
            int src, dst;
            if (is64) {
                const long long* p = (const long long*)eidx;
                src = (int)p[e];
                dst = (int)p[(size_t)E + e];
            } else {
                const int* p = (const int*)eidx;
                src = p[e];
                dst = p[E + e];
            }
            int pos = atomicAdd(&g_cur[dst], 1);
            g_esrc[pos] = src;
        }
    }
}

// ================= gather: agg[n] = sum x[src] (half rows, fp32 accum) =============
// 2 threads/node: part0 -> 16B blocks {0,1} (cols 0-15), part1 -> blocks {2,3,4}
template <int PART>
__device__ __forceinline__ void gather_part(int node) {
    const int j0 = (PART == 0) ? 0 : 2;
    const int NJ = (PART == 0) ? 2 : 3;
    int beg = g_off[node], end = g_off[node + 1];
    float acc[NJ * 8];
#pragma unroll
    for (int i = 0; i < NJ * 8; i++) acc[i] = 0.f;

    int e = beg;
    for (; e + 1 < end; e += 2) {
        int s0 = g_esrc[e], s1 = g_esrc[e + 1];
        const uint4* x0 = (const uint4*)(g_xc + (size_t)s0 * 80 + 40) + j0;
        const uint4* x1 = (const uint4*)(g_xc + (size_t)s1 * 80 + 40) + j0;
        uint4 v0[NJ], v1[NJ];
#pragma unroll
        for (int j = 0; j < NJ; j++) v0[j] = x0[j];
#pragma unroll
        for (int j = 0; j < NJ; j++) v1[j] = x1[j];
#pragma unroll
        for (int j = 0; j < NJ; j++) {
            const __half2* h0 = (const __half2*)&v0[j];
            const __half2* h1 = (const __half2*)&v1[j];
#pragma unroll
            for (int q = 0; q < 4; q++) {
                float2 f0 = __half22float2(h0[q]);
                float2 f1 = __half22float2(h1[q]);
                acc[j * 8 + 2 * q + 0] += f0.x + f1.x;
                acc[j * 8 + 2 * q + 1] += f0.y + f1.y;
            }
        }
    }
    if (e < end) {
        int s0 = g_esrc[e];
        const uint4* x0 = (const uint4*)(g_xc + (size_t)s0 * 80 + 40) + j0;
#pragma unroll
        for (int j = 0; j < NJ; j++) {
            uint4 v = x0[j];
            const __half2* h0 = (const __half2*)&v;
#pragma unroll
            for (int q = 0; q < 4; q++) {
                float2 f0 = __half22float2(h0[q]);
                acc[j * 8 + 2 * q + 0] += f0.x;
                acc[j * 8 + 2 * q + 1] += f0.y;
            }
        }
    }
    uint4* dst = (uint4*)(g_xc + (size_t)node * 80) + j0;
#pragma unroll
    for (int j = 0; j < NJ; j++) {
        uint4 o;
        __half2* oh = (__half2*)&o;
#pragma unroll
        for (int q = 0; q < 4; q++)
            oh[q] = __floats2half2_rn(acc[j * 8 + 2 * q], acc[j * 8 + 2 * q + 1]);
        dst[j] = o;
    }
}

__global__ void gather_kernel(int N) {
    int idx = blockIdx.x * blockDim.x + threadIdx.x;
    int node = idx >> 1;
    if (node >= N) return;
    if (idx & 1) gather_part<1>(node);
    else         gather_part<0>(node);
}

// ================= fp16 GEMM: C[M,256] = act(A[M,K] @ B[256,K]^T + bias) =============
// mma.m16n8k16.f16.f32-accum; block tile 128x128, warp tile 64x32, K-chunk 64,
// 3-stage cp.async, XOR-swizzled smem (word addr = row*32 + (c ^ ((row&7)<<2))).
__device__ __forceinline__ void mma_f16(float c[4], const uint32_t a[4], const uint32_t b[2]) {
    asm volatile(
        "mma.sync.aligned.m16n8k16.row.col.f32.f16.f16.f32 "
        "{%0,%1,%2,%3}, {%4,%5,%6,%7}, {%8,%9}, {%0,%1,%2,%3};\n"
        : "+f"(c[0]), "+f"(c[1]), "+f"(c[2]), "+f"(c[3])
        : "r"(a[0]), "r"(a[1]), "r"(a[2]), "r"(a[3]), "r"(b[0]), "r"(b[1]));
}
__device__ __forceinline__ void cpasync16(uint32_t saddr, const void* g, int sz) {
    asm volatile("cp.async.cg.shared.global [%0], [%1], 16, %2;"
                 :: "r"(saddr), "l"(g), "r"(sz));
}

#define STAGE_WORDS 8192  // A: 128x32 words (half2), B same at +4096
#define NSTAGE 3

template <int FUSE_PRED>
__global__ __launch_bounds__(256, 2)
void gemm_f16(const __half* __restrict__ A, const __half* __restrict__ B,
              const float* __restrict__ bias, __half* __restrict__ C, int M, int K,
              const float* __restrict__ w_pred, float* __restrict__ out) {
    extern __shared__ uint32_t sm[];
    uint32_t sbase = (uint32_t)__cvta_generic_to_shared(sm);

    int tid = threadIdx.x;
    int mB = blockIdx.x * 128;
    int nB = blockIdx.y * 128;
    int wid = tid >> 5, lane = tid & 31;
    int wm = wid >> 2, wn = wid & 3;
    int g = lane >> 2, t = lane & 3;
    int xg = g << 2;

    const int nk = (K + 63) / 64;

    float c[4][4][4];
#pragma unroll
    for (int i = 0; i < 4; i++)
#pragma unroll
        for (int j = 0; j < 4; j++)
#pragma unroll
            for (int r = 0; r < 4; r++) c[i][j][r] = 0.f;

    // chunk = 64 K-halves = 8 blocks of 16B per row; 128 rows x 8 blocks / 256 thr = 4 iters
    auto load_chunk = [&](int k0, int stage) {
#pragma unroll
        for (int p = 0; p < 4; p++) {
            int lin = tid + p * 256;
            int r = lin >> 3, cq = lin & 7;
            int k = k0 + cq * 8;
            bool kv = (k < K);
            int swc = (cq * 4) ^ ((r & 7) << 2);
            uint32_t so = sbase + ((stage * STAGE_WORDS + r * 32 + swc) << 2);
            {
                int m = mB + r;
                bool v = kv && (m < M);
                cpasync16(so, v ? (const void*)(A + (size_t)m * K + k) : (const void*)A,
                          v ? 16 : 0);
            }
            {
                int n = nB + r;
                cpasync16(so + (4096 << 2),
                          kv ? (const void*)(B + (size_t)n * K + k) : (const void*)B,
                          kv ? 16 : 0);
            }
        }
        asm volatile("cp.async.commit_group;");
    };

    load_chunk(0, 0);
    if (nk > 1) load_chunk(64, 1);

    for (int i = 0; i < nk; i++) {
        if (i + 2 < nk) {
            load_chunk((i + 2) * 64, (i + 2) % NSTAGE);
            asm volatile("cp.async.wait_group 2;");
        } else if (i + 1 < nk) {
            asm volatile("cp.async.wait_group 1;");
        } else {
            asm volatile("cp.async.wait_group 0;");
        }
        __syncthreads();

        const uint32_t* As = sm + (i % NSTAGE) * STAGE_WORDS;
        const uint32_t* Bs = As + 4096;
#pragma unroll
        for (int kk2 = 0; kk2 < 32; kk2 += 8) {  // 4 x k16 steps (word cols)
            int c0 = (kk2 + t) ^ xg;
            int c1 = (kk2 + t + 4) ^ xg;
            uint32_t a[4][4], b[4][2];
#pragma unroll
            for (int mt = 0; mt < 4; mt++) {
                int m = wm * 64 + mt * 16 + g;
                a[mt][0] = As[m * 32 + c0];
                a[mt][1] = As[(m + 8) * 32 + c0];
                a[mt][2] = As[m * 32 + c1];
                a[mt][3] = As[(m + 8) * 32 + c1];
            }
#pragma unroll
            for (int nt = 0; nt < 4; nt++) {
                int n = wn * 32 + nt * 8 + g;
                b[nt][0] = Bs[n * 32 + c0];
                b[nt][1] = Bs[n * 32 + c1];
            }
#pragma unroll
            for (int mt = 0; mt < 4; mt++)
#pragma unroll
                for (int nt = 0; nt < 4; nt++) mma_f16(c[mt][nt], a[mt], b[nt]);
        }
        __syncthreads();
    }

#pragma unroll
    for (int mt = 0; mt < 4; mt++) {
        int m0 = mB + wm * 64 + mt * 16 + g;
        float d0 = 0.f, d1 = 0.f;
#pragma unroll
        for (int nt = 0; nt < 4; nt++) {
            int n0 = nB + wn * 32 + nt * 8 + 2 * t;
            float bx = bias[n0], by = bias[n0 + 1];
            float v0x = lrelu(c[mt][nt][0] + bx);
            float v0y = lrelu(c[mt][nt][1] + by);
            float v1x = lrelu(c[mt][nt][2] + bx);
            float v1y = lrelu(c[mt][nt][3] + by);
            if (FUSE_PRED) {
                float wx = w_pred[n0], wy = w_pred[n0 + 1];
                d0 += v0x * wx + v0y * wy;
                d1 += v1x * wx + v1y * wy;
            } else {
                if (m0 < M)
                    *(__half2*)(C + (size_t)m0 * 256 + n0) = __floats2half2_rn(v0x, v0y);
                if (m0 + 8 < M)
                    *(__half2*)(C + (size_t)(m0 + 8) * 256 + n0) = __floats2half2_rn(v1x, v1y);
            }
        }
        if (FUSE_PRED) {
            d0 += __shfl_xor_sync(0xffffffffu, d0, 1);
            d0 += __shfl_xor_sync(0xffffffffu, d0, 2);
            d1 += __shfl_xor_sync(0xffffffffu, d1, 1);
            d1 += __shfl_xor_sync(0xffffffffu, d1, 2);
            if (t == 0) {
                if (m0 < M)     atomicAdd(out + m0, d0);
                if (m0 + 8 < M) atomicAdd(out + m0 + 8, d1);
            }
        }
    }
}

extern "C" void kernel_launch(void* const* d_in, const int* in_sizes, int n_in,
                              void* d_out, int out_size) {
    const float* pose   = (const float*)d_in[0];
    const float* views  = (const float*)d_in[1];
    const void*  eidx   = d_in[2];
    const float* w_e1   = (const float*)d_in[3];
    const float* b_e1   = (const float*)d_in[4];
    const float* w_e2   = (const float*)d_in[5];
    const float* b_e2   = (const float*)d_in[6];
    const float* w_rel  = (const float*)d_in[7];
    const float* b_rel  = (const float*)d_in[8];
    const float* w_root = (const float*)d_in[9];
    const float* w_l1   = (const float*)d_in[10];
    const float* b_l1   = (const float*)d_in[11];
    const float* w_l2   = (const float*)d_in[12];
    const float* b_l2   = (const float*)d_in[13];
    const float* w_l3   = (const float*)d_in[14];
    const float* b_l3   = (const float*)d_in[15];
    const float* w_pred = (const float*)d_in[16];
    const float* b_pred = (const float*)d_in[17];
    float* out = (float*)d_out;

    int N = in_sizes[0] / 3;
    int E = in_sizes[2] / 2;

    __half *xc, *w1, *wl, *h0, *h1;
    cudaGetSymbolAddress((void**)&xc, g_xc);
    cudaGetSymbolAddress((void**)&w1, g_w1cat);
    cudaGetSymbolAddress((void**)&wl, g_wl);
    cudaGetSymbolAddress((void**)&h0, g_h0);
    cudaGetSymbolAddress((void**)&h1, g_h1);
    int* cnt;
    cudaGetSymbolAddress((void**)&cnt, g_cnt);

    const int SMEM = NSTAGE * STAGE_WORDS * 4;  // 98304 B
    cudaFuncSetAttribute(gemm_f16<0>, cudaFuncAttributeMaxDynamicSharedMemorySize, SMEM);
    cudaFuncSetAttribute(gemm_f16<1>, cudaFuncAttributeMaxDynamicSharedMemorySize, SMEM);

    cudaMemsetAsync(cnt, 0, (size_t)N * sizeof(int));

    int nbCnt = (E + 1023) / 1024;
    int nbEnc = (N + 255) / 256;
    int nbPack = (256 * 80 + 255) / 256;
    int nbRnd = (3 * 65536 + 255) / 256;
    int nbOut = (N + 255) / 256;
    fused_front<<<nbCnt + nbEnc + nbPack + nbRnd + nbOut, 256>>>(
        eidx, E, pose, views, w_e1, b_e1, w_e2, b_e2,
        w_rel, w_root, w_l1, w_l2, w_l3, b_pred, out,
        N, nbCnt, nbEnc, nbPack, nbRnd);

    int nblk = (N + 1023) / 1024;
    scan_a<<<nblk, 1024>>>(N);
    scan_b<<<1, 1024>>>(nblk);
    scan_c<<<nblk, 1024>>>(N);

    fill_kernel<<<(E + 1023) / 1024, 256>>>(eidx, E);
    gather_kernel<<<(2 * N + 255) / 256, 256>>>(N);

    dim3 ggrid((N + 127) / 128, 2);
    gemm_f16<0><<<ggrid, 256, SMEM>>>(xc, w1, b_rel, h0, N, 80, nullptr, nullptr);
    gemm_f16<0><<<ggrid, 256, SMEM>>>(h0, wl, b_l1, h1, N, 256, nullptr, nullptr);
    gemm_f16<0><<<ggrid, 256, SMEM>>>(h1, wl + 65536, b_l2, h0, N, 256, nullptr, nullptr);
    gemm_f16<1><<<ggrid, 256, SMEM>>>(h0, wl + 2 * 65536, b_l3, nullptr, N, 256, w_pred, out);
}